// round 8
// baseline (speedup 1.0000x reference)
#include <cuda_runtime.h>
#include <cuda_bf16.h>
#include <cstdint>
#include <cstddef>

// Problem dims
#define NB   128     // batch
#define NT   256     // time steps
#define HD   1024    // hidden
#define IN   150     // input feature (J*D)
#define INP  192     // padded input feature (multiple of 64)
#define NC   60      // classes
#define G4   4096    // 4*HD

#define HDE  (3*HD)   // 3072: extended K ([hi|hi|lo] on A side)
#define INE  (3*INP)  // 576

// GEMM tiling: CTA 32(M) x 64(N), 4 warps of 16x32, K-tile 64, 4-stage ring
#define KT      64
#define NSTAGE  4
#define AROWB   144              // 64 bf16 (128B) + 16B pad
#define ATILEB  (32 * AROWB)     // 4608
#define BTILEB  (64 * AROWB)     // 9216
#define STAGEB  (ATILEB + BTILEB)  // 13824
#define GS_STRIDE 33
#define SMEM_DYN (NSTAGE * STAGEB + 64 * GS_STRIDE * 4 + 64 * 4)  // 63996 -> ~64KB

// ---------------- persistent device state ----------------
__device__ __nv_bfloat16 g_h1e[2][NB * HDE];
__device__ __nv_bfloat16 g_h2e[2][NB * HDE];
__device__ float g_c1[NB * HD];
__device__ float g_c2[NB * HD];
__device__ float g_bias1e[G4];
__device__ float g_bias2e[G4];
__device__ __nv_bfloat16 g_whh1e[G4 * HDE];
__device__ __nv_bfloat16 g_wih2e[G4 * HDE];
__device__ __nv_bfloat16 g_whh2e[G4 * HDE];
__device__ __nv_bfloat16 g_wih1e[G4 * INE];
__device__ __nv_bfloat16 g_xe[NT * NB * INE];

// ---------------- PTX helpers ----------------
__device__ __forceinline__ uint32_t smem_u32(const void* p) {
    uint32_t a;
    asm("{ .reg .u64 t; cvta.to.shared.u64 t, %1; cvt.u32.u64 %0, t; }" : "=r"(a) : "l"(p));
    return a;
}
__device__ __forceinline__ void cpasync16(uint32_t dst, const void* src) {
    asm volatile("cp.async.cg.shared.global [%0], [%1], 16;" :: "r"(dst), "l"(src));
}
#define CP_COMMIT() asm volatile("cp.async.commit_group;" ::: "memory")
#define CP_WAIT(n)  asm volatile("cp.async.wait_group %0;" :: "n"(n) : "memory")

__device__ __forceinline__ void ldsm4(uint32_t* r, uint32_t addr) {
    asm volatile("ldmatrix.sync.aligned.m8n8.x4.shared.b16 {%0,%1,%2,%3}, [%4];"
                 : "=r"(r[0]), "=r"(r[1]), "=r"(r[2]), "=r"(r[3]) : "r"(addr));
}
__device__ __forceinline__ void mma16816(float* d, const uint32_t* a, const uint32_t* b) {
    asm volatile(
        "mma.sync.aligned.m16n8k16.row.col.f32.bf16.bf16.f32 "
        "{%0,%1,%2,%3}, {%4,%5,%6,%7}, {%8,%9}, {%0,%1,%2,%3};"
        : "+f"(d[0]), "+f"(d[1]), "+f"(d[2]), "+f"(d[3])
        : "r"(a[0]), "r"(a[1]), "r"(a[2]), "r"(a[3]), "r"(b[0]), "r"(b[1]));
}

__device__ __forceinline__ float sigf(float x) { return 1.0f / (1.0f + __expf(-x)); }
__device__ __forceinline__ float tanh_f(float x) { return 2.0f / (1.0f + __expf(-2.0f * x)) - 1.0f; }

// ---------------- prep kernels (unchanged, validated) ----------------
__global__ void prep_weight_ext(const float* __restrict__ W, __nv_bfloat16* __restrict__ out,
                                int K, int KP) {
    int idx = blockIdx.x * blockDim.x + threadIdx.x;
    if (idx >= G4 * KP) return;
    int n = idx / KP, k = idx % KP;
    int g = n & 3, u = n >> 2;
    float v = (k < K) ? W[(size_t)(g * HD + u) * K + k] : 0.0f;
    __nv_bfloat16 hi = __float2bfloat16(v);
    __nv_bfloat16 lo = __float2bfloat16(v - __bfloat162float(hi));
    size_t base = (size_t)n * 3 * KP;
    out[base + k] = hi;
    out[base + KP + k] = lo;
    out[base + 2 * KP + k] = hi;
}

__global__ void prep_x_ext(const float* __restrict__ x) {
    int idx = blockIdx.x * blockDim.x + threadIdx.x;
    if (idx >= NT * NB * INP) return;
    int k = idx % INP;
    int r = idx / INP;
    int b = r % NB, t = r / NB;
    float v = (k < IN) ? x[((size_t)b * NT + t) * IN + k] : 0.0f;
    __nv_bfloat16 hi = __float2bfloat16(v);
    __nv_bfloat16 lo = __float2bfloat16(v - __bfloat162float(hi));
    size_t base = ((size_t)t * NB + b) * INE;
    g_xe[base + k] = hi;
    g_xe[base + INP + k] = hi;
    g_xe[base + 2 * INP + k] = lo;
}

__global__ void prep_state(const float* __restrict__ h1, const float* __restrict__ c1,
                           const float* __restrict__ h2, const float* __restrict__ c2,
                           const float* __restrict__ bih1, const float* __restrict__ bhh1,
                           const float* __restrict__ bih2, const float* __restrict__ bhh2) {
    int i = blockIdx.x * blockDim.x + threadIdx.x;
    if (i < NB * HD) {
        int m = i / HD, u = i % HD;
        float v1 = h1[i], v2 = h2[i];
        __nv_bfloat16 h1hi = __float2bfloat16(v1);
        __nv_bfloat16 h1lo = __float2bfloat16(v1 - __bfloat162float(h1hi));
        __nv_bfloat16 h2hi = __float2bfloat16(v2);
        __nv_bfloat16 h2lo = __float2bfloat16(v2 - __bfloat162float(h2hi));
        size_t base = (size_t)m * HDE;
        g_h1e[0][base + u] = h1hi; g_h1e[0][base + HD + u] = h1hi; g_h1e[0][base + 2 * HD + u] = h1lo;
        g_h2e[0][base + u] = h2hi; g_h2e[0][base + HD + u] = h2hi; g_h2e[0][base + 2 * HD + u] = h2lo;
        g_c1[i] = c1[i];
        g_c2[i] = c2[i];
    }
    if (i < G4) {
        int g = i & 3, u = i >> 2;
        int r = g * HD + u;
        g_bias1e[i] = bih1[r] + bhh1[r];
        g_bias2e[i] = bih2[r] + bhh2[r];
    }
}

// ---------------- combined LSTM step kernel ----------------
// Launch tl = 0..NT inclusive.
//   role 0 (blockIdx.z==0): phase0 at t=tl      (skip if tl==NT)
//   role 1 (blockIdx.z==1): phase1 at t=tl-1    (skip if tl==0)
// These are independent: phase0(tl) needs only h1(tl-1); phase1(tl-1) needs
// h1(tl-1) [read-only here too] and h2(tl-2).
// grid = (64 n-tiles, 4 m-tiles, 2 roles), block = 128 (4 warps of 16x32).
__global__ void __launch_bounds__(128)
lstm_step_combined(int tl) {
    const int role = blockIdx.z;
    if (role == 0 && tl == NT) return;
    if (role == 1 && tl == 0) return;
    const int t = (role == 0) ? tl : (tl - 1);
    const int cur = t & 1;

    extern __shared__ __align__(16) char sm[];
    const uint32_t SB = smem_u32(sm);
    float* Gs    = (float*)(sm + NSTAGE * STAGEB);
    float* biasS = Gs + 64 * GS_STRIDE;

    const int tid  = threadIdx.x;
    const int wid  = tid >> 5;
    const int lane = tid & 31;
    const int m0 = blockIdx.y * 32;
    const int n0 = blockIdx.x * 64;

    const __nv_bfloat16 *A0, *B0, *A1, *B1;
    const float* biasE;
    float* cst;
    __nv_bfloat16* houtE;
    int ld1, K1;
    if (role == 0) {
        A0 = g_h1e[cur];      B0 = g_whh1e;
        A1 = g_xe + (size_t)t * NB * INE;  B1 = g_wih1e;
        ld1 = INE; K1 = INE;
        biasE = g_bias1e; cst = g_c1; houtE = g_h1e[cur ^ 1];
    } else {
        A0 = g_h1e[cur ^ 1];  B0 = g_wih2e;
        A1 = g_h2e[cur];      B1 = g_whh2e;
        ld1 = HDE; K1 = HDE;
        biasE = g_bias2e; cst = g_c2; houtE = g_h2e[cur ^ 1];
    }
    const int T0 = HDE / KT;          // 48
    const int T1 = K1 / KT;           // 9 or 48
    const int TT = T0 + T1;

    if (tid < 64) biasS[tid] = biasE[n0 + tid];

    // loaders: A 32x64 bf16 (2x16B/thread), B 64x64 (4x16B/thread)
    const int arow = tid >> 2;            // 0..31
    const int acolB = (tid & 3) * 32;     // byte offset, 2 chunks
    const int brow = tid >> 1;            // 0..63
    const int bcolB = (tid & 1) * 64;     // byte offset, 4 chunks

    auto load_tile = [&](int tile, int stage) {
        const __nv_bfloat16 *A, *B;
        int ld, kb;
        if (tile < T0) { A = A0; B = B0; ld = HDE; kb = tile * KT; }
        else           { A = A1; B = B1; ld = ld1; kb = (tile - T0) * KT; }
        const char* ap = (const char*)(A + (size_t)(m0 + arow) * ld + kb) + acolB;
        const char* bp = (const char*)(B + (size_t)(n0 + brow) * ld + kb) + bcolB;
        uint32_t da = SB + stage * STAGEB + arow * AROWB + acolB;
        uint32_t db = SB + stage * STAGEB + ATILEB + brow * AROWB + bcolB;
        cpasync16(da,      ap);
        cpasync16(da + 16, ap + 16);
#pragma unroll
        for (int i = 0; i < 4; i++) cpasync16(db + i * 16, bp + i * 16);
        CP_COMMIT();
    };

    // ldmatrix per-lane offsets; warp tile 16(m) x 32(n)
    const int wr = wid >> 1;      // m half (16 rows each)
    const int wc = wid & 1;       // n half (32 cols each)
    const int grp = lane >> 3, lr = lane & 7;
    // A x4 order: (m0-7,k0-7),(m8-15,k0-7),(m0-7,k8-15),(m8-15,k8-15)
    const uint32_t aoff =
        (uint32_t)((wr * 16 + lr + (grp & 1) * 8) * AROWB + (grp >> 1) * 16);
    // B x4 (smem [n][k] = col-major B): (n0-7,k0-7),(n0-7,k8-15),(n8-15,k0-7),(n8-15,k8-15)
    uint32_t boff[2];
#pragma unroll
    for (int nc = 0; nc < 2; nc++)
        boff[nc] = (uint32_t)((wc * 32 + nc * 16 + lr + (grp >> 1) * 8) * AROWB
                              + (grp & 1) * 16) + ATILEB;

    float d[4][4];
#pragma unroll
    for (int nj = 0; nj < 4; nj++)
#pragma unroll
        for (int q = 0; q < 4; q++) d[nj][q] = 0.0f;

    // prologue: 3 stages in flight
    load_tile(0, 0);
    load_tile(1, 1);
    load_tile(2, 2);

    for (int c = 0; c < TT; c++) {
        const int s = c & (NSTAGE - 1);
        if (c < TT - 2)      { CP_WAIT(2); }
        else if (c == TT - 2){ CP_WAIT(1); }
        else                 { CP_WAIT(0); }
        __syncthreads();
        if (c + 3 < TT) load_tile(c + 3, (c + 3) & (NSTAGE - 1));

        const uint32_t sb = SB + s * STAGEB;
#pragma unroll
        for (int kk = 0; kk < 4; kk++) {
            uint32_t ar[4], b0r[4], b1r[4];
            ldsm4(ar,  sb + aoff    + kk * 32);
            ldsm4(b0r, sb + boff[0] + kk * 32);
            ldsm4(b1r, sb + boff[1] + kk * 32);
            mma16816(d[0], ar, b0r + 0);
            mma16816(d[1], ar, b0r + 2);
            mma16816(d[2], ar, b1r + 0);
            mma16816(d[3], ar, b1r + 2);
        }
    }
    __syncthreads();   // stages fully consumed before Gs reuse (Gs separate, but keep ordering cheap)

    // acc -> Gs [n][m]; d[nj]: {(r0,cb),(r0,cb+1),(r0+8,cb),(r0+8,cb+1)}
#pragma unroll
    for (int nj = 0; nj < 4; nj++) {
        int r0 = wr * 16 + (lane >> 2);
        int cb = wc * 32 + nj * 8 + (lane & 3) * 2;
        Gs[cb * GS_STRIDE + r0]           = d[nj][0];
        Gs[(cb + 1) * GS_STRIDE + r0]     = d[nj][1];
        Gs[cb * GS_STRIDE + r0 + 8]       = d[nj][2];
        Gs[(cb + 1) * GS_STRIDE + r0 + 8] = d[nj][3];
    }
    __syncthreads();

    // cell update: 32 m x 16 u = 512 cells, 4 per thread
    const int ubase = n0 >> 2;
#pragma unroll
    for (int r = 0; r < 4; r++) {
        int idx = tid + r * 128;
        int ml = idx & 31;
        int u  = idx >> 5;      // 0..15
        int nb = u * 4;
        float gi_ = Gs[(nb + 0) * GS_STRIDE + ml] + biasS[nb + 0];
        float gf_ = Gs[(nb + 1) * GS_STRIDE + ml] + biasS[nb + 1];
        float gg_ = Gs[(nb + 2) * GS_STRIDE + ml] + biasS[nb + 2];
        float go_ = Gs[(nb + 3) * GS_STRIDE + ml] + biasS[nb + 3];
        int ug = ubase + u;
        int m  = m0 + ml;
        int off = m * HD + ug;
        float cv = cst[off];
        float cn = sigf(gf_) * cv + sigf(gi_) * tanh_f(gg_);
        cst[off] = cn;
        float h = sigf(go_) * tanh_f(cn);
        __nv_bfloat16 hi = __float2bfloat16(h);
        __nv_bfloat16 lo = __float2bfloat16(h - __bfloat162float(hi));
        size_t hb = (size_t)m * HDE;
        houtE[hb + ug] = hi;
        houtE[hb + HD + ug] = hi;
        houtE[hb + 2 * HD + ug] = lo;
    }
}

// ---------------- final FC: out = h2 @ Wfc^T + bfc ----------------
__global__ void fc_kernel(const float* __restrict__ Wfc, const float* __restrict__ bfc,
                          float* __restrict__ out) {
    int b = blockIdx.x;
    int c = blockIdx.y;
    int lane = threadIdx.x;
    // last phase1 (t=NT-1, odd) wrote g_h2e[0]
    const __nv_bfloat16* he = &g_h2e[0][(size_t)b * HDE];
    const float* w = Wfc + (size_t)c * HD;
    float s = 0.0f;
    for (int k = lane; k < HD; k += 32) {
        float h = __bfloat162float(he[k]) + __bfloat162float(he[2 * HD + k]);
        s += h * w[k];
    }
#pragma unroll
    for (int o = 16; o > 0; o >>= 1) s += __shfl_xor_sync(0xFFFFFFFFu, s, o);
    if (lane == 0) out[b * NC + c] = s + bfc[c];
}

// ---------------- launch ----------------
extern "C" void kernel_launch(void* const* d_in, const int* in_sizes, int n_in,
                              void* d_out, int out_size) {
    (void)in_sizes; (void)n_in; (void)out_size;
    const float* x    = (const float*)d_in[0];
    const float* h1   = (const float*)d_in[1];
    const float* c1   = (const float*)d_in[2];
    const float* h2   = (const float*)d_in[3];
    const float* c2   = (const float*)d_in[4];
    const float* Wih1 = (const float*)d_in[5];
    const float* Whh1 = (const float*)d_in[6];
    const float* bih1 = (const float*)d_in[7];
    const float* bhh1 = (const float*)d_in[8];
    const float* Wih2 = (const float*)d_in[9];
    const float* Whh2 = (const float*)d_in[10];
    const float* bih2 = (const float*)d_in[11];
    const float* bhh2 = (const float*)d_in[12];
    const float* Wfc  = (const float*)d_in[13];
    const float* bfc  = (const float*)d_in[14];
    float* out = (float*)d_out;

    static int smem_set = 0;
    if (!smem_set) {
        cudaFuncSetAttribute(lstm_step_combined, cudaFuncAttributeMaxDynamicSharedMemorySize, SMEM_DYN);
        smem_set = 1;
    }

    // one-time prep
    prep_state<<<(NB * HD + 255) / 256, 256>>>(h1, c1, h2, c2, bih1, bhh1, bih2, bhh2);
    __nv_bfloat16* whh1e; cudaGetSymbolAddress((void**)&whh1e, g_whh1e);
    __nv_bfloat16* wih2e; cudaGetSymbolAddress((void**)&wih2e, g_wih2e);
    __nv_bfloat16* whh2e; cudaGetSymbolAddress((void**)&whh2e, g_whh2e);
    __nv_bfloat16* wih1e; cudaGetSymbolAddress((void**)&wih1e, g_wih1e);
    prep_weight_ext<<<(G4 * HD + 255) / 256, 256>>>(Whh1, whh1e, HD, HD);
    prep_weight_ext<<<(G4 * HD + 255) / 256, 256>>>(Wih2, wih2e, HD, HD);
    prep_weight_ext<<<(G4 * HD + 255) / 256, 256>>>(Whh2, whh2e, HD, HD);
    prep_weight_ext<<<(G4 * INP + 255) / 256, 256>>>(Wih1, wih1e, IN, INP);
    prep_x_ext<<<(NT * NB * INP + 255) / 256, 256>>>(x);

    // recurrence: one combined launch per step boundary (phase0(t) || phase1(t-1))
    dim3 grid(G4 / 64, NB / 32, 2);   // (64, 4, 2) = 512 CTAs
    for (int tl = 0; tl <= NT; tl++) {
        lstm_step_combined<<<grid, 128, SMEM_DYN>>>(tl);
    }

    fc_kernel<<<dim3(NB, NC), 32>>>(Wfc, bfc, out);
}

// round 9
// speedup vs baseline: 1.3800x; 1.3800x over previous
#include <cuda_runtime.h>
#include <cuda_bf16.h>
#include <cstdint>
#include <cstddef>

// Problem dims
#define NB   128     // batch
#define NT   256     // time steps
#define HD   1024    // hidden
#define IN   150     // input feature (J*D)
#define INP  192     // padded input feature (multiple of 64)
#define NC   60      // classes
#define G4   4096    // 4*HD

#define HDE  (3*HD)   // 3072: extended K ([hi|hi|lo] on A side)
#define INE  (3*INP)  // 576

// GEMM tiling: CTA 64(M) x 64(N), 4 warps of 32x32, K-tile 64, 4-stage ring
#define KT      64
#define NSTAGE  4
#define AROWB   144              // 64 bf16 (128B) + 16B pad
#define ATILEB  (64 * AROWB)     // 9216
#define STAGEB  (2 * ATILEB)     // 18432
#define GS_STRIDE 65
// Gs (64*65*4 = 16640 B) aliases the stage buffers (free after final sync).
#define SMEM_DYN (NSTAGE * STAGEB + 256)   // 73984 -> 3 CTAs/SM

// ---------------- persistent device state ----------------
__device__ __nv_bfloat16 g_h1e[2][NB * HDE];
__device__ __nv_bfloat16 g_h2e[2][NB * HDE];
__device__ float g_c1[NB * HD];
__device__ float g_c2[NB * HD];
__device__ float g_bias1e[G4];
__device__ float g_bias2e[G4];
__device__ __nv_bfloat16 g_whh1e[G4 * HDE];
__device__ __nv_bfloat16 g_wih2e[G4 * HDE];
__device__ __nv_bfloat16 g_whh2e[G4 * HDE];
__device__ __nv_bfloat16 g_wih1e[G4 * INE];
__device__ __nv_bfloat16 g_xe[NT * NB * INE];

// ---------------- PTX helpers ----------------
__device__ __forceinline__ uint32_t smem_u32(const void* p) {
    uint32_t a;
    asm("{ .reg .u64 t; cvta.to.shared.u64 t, %1; cvt.u32.u64 %0, t; }" : "=r"(a) : "l"(p));
    return a;
}
__device__ __forceinline__ void cpasync16(uint32_t dst, const void* src) {
    asm volatile("cp.async.cg.shared.global [%0], [%1], 16;" :: "r"(dst), "l"(src));
}
#define CP_COMMIT() asm volatile("cp.async.commit_group;" ::: "memory")
#define CP_WAIT(n)  asm volatile("cp.async.wait_group %0;" :: "n"(n) : "memory")

__device__ __forceinline__ void ldsm4(uint32_t* r, uint32_t addr) {
    asm volatile("ldmatrix.sync.aligned.m8n8.x4.shared.b16 {%0,%1,%2,%3}, [%4];"
                 : "=r"(r[0]), "=r"(r[1]), "=r"(r[2]), "=r"(r[3]) : "r"(addr));
}
__device__ __forceinline__ void mma16816(float* d, const uint32_t* a, const uint32_t* b) {
    asm volatile(
        "mma.sync.aligned.m16n8k16.row.col.f32.bf16.bf16.f32 "
        "{%0,%1,%2,%3}, {%4,%5,%6,%7}, {%8,%9}, {%0,%1,%2,%3};"
        : "+f"(d[0]), "+f"(d[1]), "+f"(d[2]), "+f"(d[3])
        : "r"(a[0]), "r"(a[1]), "r"(a[2]), "r"(a[3]), "r"(b[0]), "r"(b[1]));
}

__device__ __forceinline__ float sigf(float x) { return 1.0f / (1.0f + __expf(-x)); }
__device__ __forceinline__ float tanh_f(float x) { return 2.0f / (1.0f + __expf(-2.0f * x)) - 1.0f; }

// ---------------- prep kernels (validated) ----------------
__global__ void prep_weight_ext(const float* __restrict__ W, __nv_bfloat16* __restrict__ out,
                                int K, int KP) {
    int idx = blockIdx.x * blockDim.x + threadIdx.x;
    if (idx >= G4 * KP) return;
    int n = idx / KP, k = idx % KP;
    int g = n & 3, u = n >> 2;
    float v = (k < K) ? W[(size_t)(g * HD + u) * K + k] : 0.0f;
    __nv_bfloat16 hi = __float2bfloat16(v);
    __nv_bfloat16 lo = __float2bfloat16(v - __bfloat162float(hi));
    size_t base = (size_t)n * 3 * KP;
    out[base + k] = hi;
    out[base + KP + k] = lo;
    out[base + 2 * KP + k] = hi;
}

__global__ void prep_x_ext(const float* __restrict__ x) {
    int idx = blockIdx.x * blockDim.x + threadIdx.x;
    if (idx >= NT * NB * INP) return;
    int k = idx % INP;
    int r = idx / INP;
    int b = r % NB, t = r / NB;
    float v = (k < IN) ? x[((size_t)b * NT + t) * IN + k] : 0.0f;
    __nv_bfloat16 hi = __float2bfloat16(v);
    __nv_bfloat16 lo = __float2bfloat16(v - __bfloat162float(hi));
    size_t base = ((size_t)t * NB + b) * INE;
    g_xe[base + k] = hi;
    g_xe[base + INP + k] = hi;
    g_xe[base + 2 * INP + k] = lo;
}

__global__ void prep_state(const float* __restrict__ h1, const float* __restrict__ c1,
                           const float* __restrict__ h2, const float* __restrict__ c2,
                           const float* __restrict__ bih1, const float* __restrict__ bhh1,
                           const float* __restrict__ bih2, const float* __restrict__ bhh2) {
    int i = blockIdx.x * blockDim.x + threadIdx.x;
    if (i < NB * HD) {
        int m = i / HD, u = i % HD;
        float v1 = h1[i], v2 = h2[i];
        __nv_bfloat16 h1hi = __float2bfloat16(v1);
        __nv_bfloat16 h1lo = __float2bfloat16(v1 - __bfloat162float(h1hi));
        __nv_bfloat16 h2hi = __float2bfloat16(v2);
        __nv_bfloat16 h2lo = __float2bfloat16(v2 - __bfloat162float(h2hi));
        size_t base = (size_t)m * HDE;
        g_h1e[0][base + u] = h1hi; g_h1e[0][base + HD + u] = h1hi; g_h1e[0][base + 2 * HD + u] = h1lo;
        g_h2e[0][base + u] = h2hi; g_h2e[0][base + HD + u] = h2hi; g_h2e[0][base + 2 * HD + u] = h2lo;
        g_c1[i] = c1[i];
        g_c2[i] = c2[i];
    }
    if (i < G4) {
        int g = i & 3, u = i >> 2;
        int r = g * HD + u;
        g_bias1e[i] = bih1[r] + bhh1[r];
        g_bias2e[i] = bih2[r] + bhh2[r];
    }
}

// ---------------- combined LSTM step kernel ----------------
// tl = 0..NT.  role 0: phase0 at t=tl (skip if tl==NT)
//              role 1: phase1 at t=tl-1 (skip if tl==0)
// Independent: phase0(tl) reads h1[tl&1], writes h1[(tl&1)^1], c1.
//              phase1(tl-1) reads h1[tl&1] and h2[(tl-1)&1], writes h2[tl&1], c2.
// grid = (64 n-tiles, 2 m-tiles, 2 roles), block = 128 (4 warps of 32x32).
__global__ void __launch_bounds__(128)
lstm_step_combined(int tl) {
    const int role = blockIdx.z;
    if (role == 0 && tl == NT) return;
    if (role == 1 && tl == 0) return;
    const int t = (role == 0) ? tl : (tl - 1);
    const int cur = t & 1;

    extern __shared__ __align__(16) char sm[];
    const uint32_t SB = smem_u32(sm);
    float* Gs    = (float*)sm;                       // aliases stage buffers (used after final sync)
    float* biasS = (float*)(sm + NSTAGE * STAGEB);   // 64 floats

    const int tid  = threadIdx.x;
    const int wid  = tid >> 5;
    const int lane = tid & 31;
    const int m0 = blockIdx.y * 64;
    const int n0 = blockIdx.x * 64;

    const __nv_bfloat16 *A0, *B0, *A1, *B1;
    const float* biasE;
    float* cst;
    __nv_bfloat16* houtE;
    int ld1, K1;
    if (role == 0) {
        A0 = g_h1e[cur];      B0 = g_whh1e;
        A1 = g_xe + (size_t)t * NB * INE;  B1 = g_wih1e;
        ld1 = INE; K1 = INE;
        biasE = g_bias1e; cst = g_c1; houtE = g_h1e[cur ^ 1];
    } else {
        A0 = g_h1e[cur ^ 1];  B0 = g_wih2e;
        A1 = g_h2e[cur];      B1 = g_whh2e;
        ld1 = HDE; K1 = HDE;
        biasE = g_bias2e; cst = g_c2; houtE = g_h2e[cur ^ 1];
    }
    const int T0 = HDE / KT;          // 48
    const int T1 = K1 / KT;           // 9 or 48
    const int TT = T0 + T1;

    float biasR = (tid < 64) ? biasE[n0 + tid] : 0.0f;

    // loaders: rows 0..63, half-row (32 bf16 = 64B) per thread, 4x16B each for A and B
    const int arow = tid >> 1;
    const int acolB = (tid & 1) * 64;

    auto load_tile = [&](int tile, int stage) {
        const __nv_bfloat16 *A, *B;
        int ld, kb;
        if (tile < T0) { A = A0; B = B0; ld = HDE; kb = tile * KT; }
        else           { A = A1; B = B1; ld = ld1; kb = (tile - T0) * KT; }
        const char* ap = (const char*)(A + (size_t)(m0 + arow) * ld + kb) + acolB;
        const char* bp = (const char*)(B + (size_t)(n0 + arow) * ld + kb) + acolB;
        uint32_t da = SB + stage * STAGEB + arow * AROWB + acolB;
        uint32_t db = da + ATILEB;
#pragma unroll
        for (int i = 0; i < 4; i++) {
            cpasync16(da + i * 16, ap + i * 16);
            cpasync16(db + i * 16, bp + i * 16);
        }
        CP_COMMIT();
    };

    // ldmatrix per-lane offsets (R7-validated)
    // A (x4): (m0-7,k0-7),(m8-15,k0-7),(m0-7,k8-15),(m8-15,k8-15)
    const int wr = wid >> 1;      // m half
    const int wc = wid & 1;       // n half
    const int grp = lane >> 3, lr = lane & 7;
    uint32_t aoff[2], boff[2];
#pragma unroll
    for (int mi = 0; mi < 2; mi++)
        aoff[mi] = (uint32_t)((wr * 32 + mi * 16 + lr + (grp & 1) * 8) * AROWB + (grp >> 1) * 16);
    // B (x4; smem [n][k] = col-major B): (n0-7,k0-7),(n0-7,k8-15),(n8-15,k0-7),(n8-15,k8-15)
#pragma unroll
    for (int nc = 0; nc < 2; nc++)
        boff[nc] = (uint32_t)((wc * 32 + nc * 16 + lr + (grp >> 1) * 8) * AROWB + (grp & 1) * 16) + ATILEB;

    float d[2][4][4];
#pragma unroll
    for (int mi = 0; mi < 2; mi++)
#pragma unroll
        for (int nj = 0; nj < 4; nj++)
#pragma unroll
            for (int q = 0; q < 4; q++) d[mi][nj][q] = 0.0f;

    // prologue: 3 stages in flight
    load_tile(0, 0);
    load_tile(1, 1);
    load_tile(2, 2);

    for (int c = 0; c < TT; c++) {
        const int s = c & (NSTAGE - 1);
        if (c < TT - 2)       { CP_WAIT(2); }
        else if (c == TT - 2) { CP_WAIT(1); }
        else                  { CP_WAIT(0); }
        __syncthreads();
        // stage (c+3)&3 == (c-1)&3 was fully consumed at iteration c-1 (all warps
        // passed this barrier), so refilling it now is safe.
        if (c + 3 < TT) load_tile(c + 3, (c + 3) & (NSTAGE - 1));

        const uint32_t sb = SB + s * STAGEB;
#pragma unroll
        for (int kk = 0; kk < 4; kk++) {
            uint32_t a0r[4], a1r[4], b0r[4], b1r[4];
            ldsm4(a0r, sb + aoff[0] + kk * 32);
            ldsm4(a1r, sb + aoff[1] + kk * 32);
            ldsm4(b0r, sb + boff[0] + kk * 32);
            ldsm4(b1r, sb + boff[1] + kk * 32);
            mma16816(d[0][0], a0r, b0r + 0);
            mma16816(d[0][1], a0r, b0r + 2);
            mma16816(d[0][2], a0r, b1r + 0);
            mma16816(d[0][3], a0r, b1r + 2);
            mma16816(d[1][0], a1r, b0r + 0);
            mma16816(d[1][1], a1r, b0r + 2);
            mma16816(d[1][2], a1r, b1r + 0);
            mma16816(d[1][3], a1r, b1r + 2);
        }
    }
    __syncthreads();   // all ldsm reads done; stage smem now reusable as Gs

    if (tid < 64) biasS[tid] = biasR;

    // acc -> Gs [n][m]
#pragma unroll
    for (int mi = 0; mi < 2; mi++) {
#pragma unroll
        for (int nj = 0; nj < 4; nj++) {
            int r0 = wr * 32 + mi * 16 + (lane >> 2);
            int cb = wc * 32 + nj * 8 + (lane & 3) * 2;
            Gs[cb * GS_STRIDE + r0]           = d[mi][nj][0];
            Gs[(cb + 1) * GS_STRIDE + r0]     = d[mi][nj][1];
            Gs[cb * GS_STRIDE + r0 + 8]       = d[mi][nj][2];
            Gs[(cb + 1) * GS_STRIDE + r0 + 8] = d[mi][nj][3];
        }
    }
    __syncthreads();

    // cell update: 64 m x 16 u = 1024 cells, 8 per thread
    const int ubase = n0 >> 2;
#pragma unroll
    for (int r = 0; r < 8; r++) {
        int idx = tid + r * 128;
        int ml = idx & 63;
        int u  = idx >> 6;      // 0..15
        int nb = u * 4;
        float gi_ = Gs[(nb + 0) * GS_STRIDE + ml] + biasS[nb + 0];
        float gf_ = Gs[(nb + 1) * GS_STRIDE + ml] + biasS[nb + 1];
        float gg_ = Gs[(nb + 2) * GS_STRIDE + ml] + biasS[nb + 2];
        float go_ = Gs[(nb + 3) * GS_STRIDE + ml] + biasS[nb + 3];
        int ug = ubase + u;
        int m  = m0 + ml;
        int off = m * HD + ug;
        float cv = cst[off];
        float cn = sigf(gf_) * cv + sigf(gi_) * tanh_f(gg_);
        cst[off] = cn;
        float h = sigf(go_) * tanh_f(cn);
        __nv_bfloat16 hi = __float2bfloat16(h);
        __nv_bfloat16 lo = __float2bfloat16(h - __bfloat162float(hi));
        size_t hb = (size_t)m * HDE;
        houtE[hb + ug] = hi;
        houtE[hb + HD + ug] = hi;
        houtE[hb + 2 * HD + ug] = lo;
    }
}

// ---------------- final FC: out = h2 @ Wfc^T + bfc ----------------
__global__ void fc_kernel(const float* __restrict__ Wfc, const float* __restrict__ bfc,
                          float* __restrict__ out) {
    int b = blockIdx.x;
    int c = blockIdx.y;
    int lane = threadIdx.x;
    // last phase1 (t=NT-1, odd) wrote g_h2e[0]
    const __nv_bfloat16* he = &g_h2e[0][(size_t)b * HDE];
    const float* w = Wfc + (size_t)c * HD;
    float s = 0.0f;
    for (int k = lane; k < HD; k += 32) {
        float h = __bfloat162float(he[k]) + __bfloat162float(he[2 * HD + k]);
        s += h * w[k];
    }
#pragma unroll
    for (int o = 16; o > 0; o >>= 1) s += __shfl_xor_sync(0xFFFFFFFFu, s, o);
    if (lane == 0) out[b * NC + c] = s + bfc[c];
}

// ---------------- launch ----------------
extern "C" void kernel_launch(void* const* d_in, const int* in_sizes, int n_in,
                              void* d_out, int out_size) {
    (void)in_sizes; (void)n_in; (void)out_size;
    const float* x    = (const float*)d_in[0];
    const float* h1   = (const float*)d_in[1];
    const float* c1   = (const float*)d_in[2];
    const float* h2   = (const float*)d_in[3];
    const float* c2   = (const float*)d_in[4];
    const float* Wih1 = (const float*)d_in[5];
    const float* Whh1 = (const float*)d_in[6];
    const float* bih1 = (const float*)d_in[7];
    const float* bhh1 = (const float*)d_in[8];
    const float* Wih2 = (const float*)d_in[9];
    const float* Whh2 = (const float*)d_in[10];
    const float* bih2 = (const float*)d_in[11];
    const float* bhh2 = (const float*)d_in[12];
    const float* Wfc  = (const float*)d_in[13];
    const float* bfc  = (const float*)d_in[14];
    float* out = (float*)d_out;

    static int smem_set = 0;
    if (!smem_set) {
        cudaFuncSetAttribute(lstm_step_combined, cudaFuncAttributeMaxDynamicSharedMemorySize, SMEM_DYN);
        smem_set = 1;
    }

    // one-time prep
    prep_state<<<(NB * HD + 255) / 256, 256>>>(h1, c1, h2, c2, bih1, bhh1, bih2, bhh2);
    __nv_bfloat16* whh1e; cudaGetSymbolAddress((void**)&whh1e, g_whh1e);
    __nv_bfloat16* wih2e; cudaGetSymbolAddress((void**)&wih2e, g_wih2e);
    __nv_bfloat16* whh2e; cudaGetSymbolAddress((void**)&whh2e, g_whh2e);
    __nv_bfloat16* wih1e; cudaGetSymbolAddress((void**)&wih1e, g_wih1e);
    prep_weight_ext<<<(G4 * HD + 255) / 256, 256>>>(Whh1, whh1e, HD, HD);
    prep_weight_ext<<<(G4 * HD + 255) / 256, 256>>>(Wih2, wih2e, HD, HD);
    prep_weight_ext<<<(G4 * HD + 255) / 256, 256>>>(Whh2, whh2e, HD, HD);
    prep_weight_ext<<<(G4 * INP + 255) / 256, 256>>>(Wih1, wih1e, IN, INP);
    prep_x_ext<<<(NT * NB * INP + 255) / 256, 256>>>(x);

    // recurrence: one combined launch per step boundary (phase0(tl) || phase1(tl-1))
    dim3 grid(G4 / 64, NB / 64, 2);   // (64, 2, 2) = 256 CTAs
    for (int tl = 0; tl <= NT; tl++) {
        lstm_step_combined<<<grid, 128, SMEM_DYN>>>(tl);
    }

    fc_kernel<<<dim3(NB, NC), 32>>>(Wfc, bfc, out);
}

// round 10
// speedup vs baseline: 1.4910x; 1.0805x over previous
#include <cuda_runtime.h>
#include <cuda_bf16.h>
#include <cstdint>
#include <cstddef>

// Problem dims
#define NB   128     // batch
#define NT   256     // time steps
#define HD   1024    // hidden
#define IN   150     // input feature (J*D)
#define INP  192     // padded input feature (multiple of 64)
#define NC   60      // classes
#define G4   4096    // 4*HD

#define HDE  (3*HD)   // 3072: extended K ([hi|hi|lo] on A side)
#define INE  (3*INP)  // 576

// GEMM tiling: CTA 128(M) x 64(N), 8 warps of 32x32, K-tile 64, 4-stage ring
#define KT      64
#define NSTAGE  4
#define AROWB   144               // 64 bf16 (128B) + 16B pad
#define ATILEB  (128 * AROWB)     // 18432
#define BTILEB  (64 * AROWB)      // 9216
#define STAGEB  (ATILEB + BTILEB) // 27648
#define GS_STRIDE 129
// Gs (64*129*4 = 33024 B) aliases the stage buffers (free after final sync).
#define SMEM_DYN (NSTAGE * STAGEB + 256)   // 110848 -> 1 CTA/SM (by smem), grid <= #SM anyway

// ---------------- persistent device state ----------------
__device__ __nv_bfloat16 g_h1e[2][NB * HDE];
__device__ __nv_bfloat16 g_h2e[2][NB * HDE];
__device__ float g_c1[NB * HD];
__device__ float g_c2[NB * HD];
__device__ float g_bias1e[G4];
__device__ float g_bias2e[G4];
__device__ __nv_bfloat16 g_whh1e[G4 * HDE];
__device__ __nv_bfloat16 g_wih2e[G4 * HDE];
__device__ __nv_bfloat16 g_whh2e[G4 * HDE];
__device__ __nv_bfloat16 g_wih1e[G4 * INE];
__device__ __nv_bfloat16 g_xe[NT * NB * INE];

// ---------------- PTX helpers ----------------
__device__ __forceinline__ uint32_t smem_u32(const void* p) {
    uint32_t a;
    asm("{ .reg .u64 t; cvta.to.shared.u64 t, %1; cvt.u32.u64 %0, t; }" : "=r"(a) : "l"(p));
    return a;
}
__device__ __forceinline__ void cpasync16(uint32_t dst, const void* src) {
    asm volatile("cp.async.cg.shared.global [%0], [%1], 16;" :: "r"(dst), "l"(src));
}
#define CP_COMMIT() asm volatile("cp.async.commit_group;" ::: "memory")
#define CP_WAIT(n)  asm volatile("cp.async.wait_group %0;" :: "n"(n) : "memory")

__device__ __forceinline__ void ldsm4(uint32_t* r, uint32_t addr) {
    asm volatile("ldmatrix.sync.aligned.m8n8.x4.shared.b16 {%0,%1,%2,%3}, [%4];"
                 : "=r"(r[0]), "=r"(r[1]), "=r"(r[2]), "=r"(r[3]) : "r"(addr));
}
__device__ __forceinline__ void mma16816(float* d, const uint32_t* a, const uint32_t* b) {
    asm volatile(
        "mma.sync.aligned.m16n8k16.row.col.f32.bf16.bf16.f32 "
        "{%0,%1,%2,%3}, {%4,%5,%6,%7}, {%8,%9}, {%0,%1,%2,%3};"
        : "+f"(d[0]), "+f"(d[1]), "+f"(d[2]), "+f"(d[3])
        : "r"(a[0]), "r"(a[1]), "r"(a[2]), "r"(a[3]), "r"(b[0]), "r"(b[1]));
}

__device__ __forceinline__ float sigf(float x) { return 1.0f / (1.0f + __expf(-x)); }
__device__ __forceinline__ float tanh_f(float x) { return 2.0f / (1.0f + __expf(-2.0f * x)) - 1.0f; }

// ---------------- single merged prep kernel ----------------
// grid = (24576, 6); blockIdx.y dispatches sub-task. One launch total, so that
// ncu -s 5 lands on a step kernel.
__device__ __forceinline__ void split_w(const float* W, __nv_bfloat16* out, int K, int KP, int idx) {
    if (idx >= G4 * KP) return;
    int n = idx / KP, k = idx % KP;
    int g = n & 3, u = n >> 2;
    float v = (k < K) ? W[(size_t)(g * HD + u) * K + k] : 0.0f;
    __nv_bfloat16 hi = __float2bfloat16(v);
    __nv_bfloat16 lo = __float2bfloat16(v - __bfloat162float(hi));
    size_t base = (size_t)n * 3 * KP;
    out[base + k] = hi;
    out[base + KP + k] = lo;
    out[base + 2 * KP + k] = hi;
}

__global__ void prep_all(const float* __restrict__ x,
                         const float* __restrict__ h1, const float* __restrict__ c1,
                         const float* __restrict__ h2, const float* __restrict__ c2,
                         const float* __restrict__ bih1, const float* __restrict__ bhh1,
                         const float* __restrict__ bih2, const float* __restrict__ bhh2,
                         const float* __restrict__ Wih1, const float* __restrict__ Whh1,
                         const float* __restrict__ Wih2, const float* __restrict__ Whh2) {
    int idx = blockIdx.x * blockDim.x + threadIdx.x;
    int task = blockIdx.y;
    if (task == 0) {
        if (idx < NB * HD) {
            int m = idx / HD, u = idx % HD;
            float v1 = h1[idx], v2 = h2[idx];
            __nv_bfloat16 h1hi = __float2bfloat16(v1);
            __nv_bfloat16 h1lo = __float2bfloat16(v1 - __bfloat162float(h1hi));
            __nv_bfloat16 h2hi = __float2bfloat16(v2);
            __nv_bfloat16 h2lo = __float2bfloat16(v2 - __bfloat162float(h2hi));
            size_t base = (size_t)m * HDE;
            g_h1e[0][base + u] = h1hi; g_h1e[0][base + HD + u] = h1hi; g_h1e[0][base + 2 * HD + u] = h1lo;
            g_h2e[0][base + u] = h2hi; g_h2e[0][base + HD + u] = h2hi; g_h2e[0][base + 2 * HD + u] = h2lo;
            g_c1[idx] = c1[idx];
            g_c2[idx] = c2[idx];
        }
        if (idx < G4) {
            int g = idx & 3, u = idx >> 2;
            int r = g * HD + u;
            g_bias1e[idx] = bih1[r] + bhh1[r];
            g_bias2e[idx] = bih2[r] + bhh2[r];
        }
    } else if (task == 1) {
        split_w(Whh1, g_whh1e, HD, HD, idx);
    } else if (task == 2) {
        split_w(Wih2, g_wih2e, HD, HD, idx);
    } else if (task == 3) {
        split_w(Whh2, g_whh2e, HD, HD, idx);
    } else if (task == 4) {
        split_w(Wih1, g_wih1e, IN, INP, idx);
    } else {
        if (idx >= NT * NB * INP) return;
        int k = idx % INP;
        int r = idx / INP;
        int b = r % NB, t = r / NB;
        float v = (k < IN) ? x[((size_t)b * NT + t) * IN + k] : 0.0f;
        __nv_bfloat16 hi = __float2bfloat16(v);
        __nv_bfloat16 lo = __float2bfloat16(v - __bfloat162float(hi));
        size_t base = ((size_t)t * NB + b) * INE;
        g_xe[base + k] = hi;
        g_xe[base + INP + k] = hi;
        g_xe[base + 2 * INP + k] = lo;
    }
}

// ---------------- combined LSTM step kernel ----------------
// tl = 0..NT.  role 0 (blockIdx.z==0): phase0 at t=tl (skip if tl==NT)
//              role 1 (blockIdx.z==1): phase1 at t=tl-1 (skip if tl==0)
// grid = (64 n-tiles, 1, 2 roles) = 128 CTAs -> exactly <=1 CTA per SM.
// block = 256 (8 warps): warp tile 32x32; m-quarter = wid>>1, n-half = wid&1.
__global__ void __launch_bounds__(256)
lstm_step_combined(int tl) {
    const int role = blockIdx.z;
    if (role == 0 && tl == NT) return;
    if (role == 1 && tl == 0) return;
    const int t = (role == 0) ? tl : (tl - 1);
    const int cur = t & 1;

    extern __shared__ __align__(16) char sm[];
    const uint32_t SB = smem_u32(sm);
    float* Gs    = (float*)sm;                       // aliases stage buffers (used after final sync)
    float* biasS = (float*)(sm + NSTAGE * STAGEB);   // 64 floats

    const int tid  = threadIdx.x;
    const int wid  = tid >> 5;
    const int lane = tid & 31;
    const int n0 = blockIdx.x * 64;

    const __nv_bfloat16 *A0, *B0, *A1, *B1;
    const float* biasE;
    float* cst;
    __nv_bfloat16* houtE;
    int ld1, K1;
    if (role == 0) {
        A0 = g_h1e[cur];      B0 = g_whh1e;
        A1 = g_xe + (size_t)t * NB * INE;  B1 = g_wih1e;
        ld1 = INE; K1 = INE;
        biasE = g_bias1e; cst = g_c1; houtE = g_h1e[cur ^ 1];
    } else {
        A0 = g_h1e[cur ^ 1];  B0 = g_wih2e;
        A1 = g_h2e[cur];      B1 = g_whh2e;
        ld1 = HDE; K1 = HDE;
        biasE = g_bias2e; cst = g_c2; houtE = g_h2e[cur ^ 1];
    }
    const int T0 = HDE / KT;          // 48
    const int T1 = K1 / KT;           // 9 or 48
    const int TT = T0 + T1;

    float biasR = (tid < 64) ? biasE[n0 + tid] : 0.0f;

    // loaders: A 128 rows x 64 cols (half-row 64B per thread, 4x16B);
    //          B 64 rows x 64 cols (quarter-row 32B per thread, 2x16B)
    const int arow = tid >> 1;            // 0..127
    const int acolB = (tid & 1) * 64;
    const int brow = tid >> 2;            // 0..63
    const int bcolB = (tid & 3) * 32;

    auto load_tile = [&](int tile, int stage) {
        const __nv_bfloat16 *A, *B;
        int ld, kb;
        if (tile < T0) { A = A0; B = B0; ld = HDE; kb = tile * KT; }
        else           { A = A1; B = B1; ld = ld1; kb = (tile - T0) * KT; }
        const char* ap = (const char*)(A + (size_t)arow * ld + kb) + acolB;
        const char* bp = (const char*)(B + (size_t)(n0 + brow) * ld + kb) + bcolB;
        uint32_t da = SB + stage * STAGEB + arow * AROWB + acolB;
        uint32_t db = SB + stage * STAGEB + ATILEB + brow * AROWB + bcolB;
#pragma unroll
        for (int i = 0; i < 4; i++) cpasync16(da + i * 16, ap + i * 16);
        cpasync16(db,      bp);
        cpasync16(db + 16, bp + 16);
        CP_COMMIT();
    };

    // ldmatrix per-lane offsets (R7-validated maps, m-quarter extended)
    const int wr = wid >> 1;      // m quarter (0..3), rows wr*32..+31
    const int wc = wid & 1;       // n half
    const int grp = lane >> 3, lr = lane & 7;
    uint32_t aoff[2], boff[2];
#pragma unroll
    for (int mi = 0; mi < 2; mi++)
        aoff[mi] = (uint32_t)((wr * 32 + mi * 16 + lr + (grp & 1) * 8) * AROWB + (grp >> 1) * 16);
#pragma unroll
    for (int nc = 0; nc < 2; nc++)
        boff[nc] = (uint32_t)((wc * 32 + nc * 16 + lr + (grp >> 1) * 8) * AROWB + (grp & 1) * 16) + ATILEB;

    float d[2][4][4];
#pragma unroll
    for (int mi = 0; mi < 2; mi++)
#pragma unroll
        for (int nj = 0; nj < 4; nj++)
#pragma unroll
            for (int q = 0; q < 4; q++) d[mi][nj][q] = 0.0f;

    // prologue: 3 stages in flight
    load_tile(0, 0);
    load_tile(1, 1);
    load_tile(2, 2);

    for (int c = 0; c < TT; c++) {
        const int s = c & (NSTAGE - 1);
        if (c < TT - 2)       { CP_WAIT(2); }
        else if (c == TT - 2) { CP_WAIT(1); }
        else                  { CP_WAIT(0); }
        __syncthreads();
        if (c + 3 < TT) load_tile(c + 3, (c + 3) & (NSTAGE - 1));

        const uint32_t sb = SB + s * STAGEB;
#pragma unroll
        for (int kk = 0; kk < 4; kk++) {
            uint32_t a0r[4], a1r[4], b0r[4], b1r[4];
            ldsm4(a0r, sb + aoff[0] + kk * 32);
            ldsm4(a1r, sb + aoff[1] + kk * 32);
            ldsm4(b0r, sb + boff[0] + kk * 32);
            ldsm4(b1r, sb + boff[1] + kk * 32);
            mma16816(d[0][0], a0r, b0r + 0);
            mma16816(d[0][1], a0r, b0r + 2);
            mma16816(d[0][2], a0r, b1r + 0);
            mma16816(d[0][3], a0r, b1r + 2);
            mma16816(d[1][0], a1r, b0r + 0);
            mma16816(d[1][1], a1r, b0r + 2);
            mma16816(d[1][2], a1r, b1r + 0);
            mma16816(d[1][3], a1r, b1r + 2);
        }
    }
    __syncthreads();   // all ldsm reads done; stage smem now reusable as Gs

    if (tid < 64) biasS[tid] = biasR;

    // acc -> Gs [n][m]
#pragma unroll
    for (int mi = 0; mi < 2; mi++) {
#pragma unroll
        for (int nj = 0; nj < 4; nj++) {
            int r0 = wr * 32 + mi * 16 + (lane >> 2);
            int cb = wc * 32 + nj * 8 + (lane & 3) * 2;
            Gs[cb * GS_STRIDE + r0]           = d[mi][nj][0];
            Gs[(cb + 1) * GS_STRIDE + r0]     = d[mi][nj][1];
            Gs[cb * GS_STRIDE + r0 + 8]       = d[mi][nj][2];
            Gs[(cb + 1) * GS_STRIDE + r0 + 8] = d[mi][nj][3];
        }
    }
    __syncthreads();

    // cell update: 128 m x 16 u = 2048 cells, 8 per thread
    const int ubase = n0 >> 2;
#pragma unroll
    for (int r = 0; r < 8; r++) {
        int idx = tid + r * 256;
        int ml = idx & 127;     // m
        int u  = idx >> 7;      // 0..15
        int nb = u * 4;
        float gi_ = Gs[(nb + 0) * GS_STRIDE + ml] + biasS[nb + 0];
        float gf_ = Gs[(nb + 1) * GS_STRIDE + ml] + biasS[nb + 1];
        float gg_ = Gs[(nb + 2) * GS_STRIDE + ml] + biasS[nb + 2];
        float go_ = Gs[(nb + 3) * GS_STRIDE + ml] + biasS[nb + 3];
        int ug = ubase + u;
        int off = ml * HD + ug;
        float cv = cst[off];
        float cn = sigf(gf_) * cv + sigf(gi_) * tanh_f(gg_);
        cst[off] = cn;
        float h = sigf(go_) * tanh_f(cn);
        __nv_bfloat16 hi = __float2bfloat16(h);
        __nv_bfloat16 lo = __float2bfloat16(h - __bfloat162float(hi));
        size_t hb = (size_t)ml * HDE;
        houtE[hb + ug] = hi;
        houtE[hb + HD + ug] = hi;
        houtE[hb + 2 * HD + ug] = lo;
    }
}

// ---------------- final FC: out = h2 @ Wfc^T + bfc ----------------
__global__ void fc_kernel(const float* __restrict__ Wfc, const float* __restrict__ bfc,
                          float* __restrict__ out) {
    int b = blockIdx.x;
    int c = blockIdx.y;
    int lane = threadIdx.x;
    // last phase1 (t=NT-1, odd) wrote g_h2e[0]
    const __nv_bfloat16* he = &g_h2e[0][(size_t)b * HDE];
    const float* w = Wfc + (size_t)c * HD;
    float s = 0.0f;
    for (int k = lane; k < HD; k += 32) {
        float h = __bfloat162float(he[k]) + __bfloat162float(he[2 * HD + k]);
        s += h * w[k];
    }
#pragma unroll
    for (int o = 16; o > 0; o >>= 1) s += __shfl_xor_sync(0xFFFFFFFFu, s, o);
    if (lane == 0) out[b * NC + c] = s + bfc[c];
}

// ---------------- launch ----------------
extern "C" void kernel_launch(void* const* d_in, const int* in_sizes, int n_in,
                              void* d_out, int out_size) {
    (void)in_sizes; (void)n_in; (void)out_size;
    const float* x    = (const float*)d_in[0];
    const float* h1   = (const float*)d_in[1];
    const float* c1   = (const float*)d_in[2];
    const float* h2   = (const float*)d_in[3];
    const float* c2   = (const float*)d_in[4];
    const float* Wih1 = (const float*)d_in[5];
    const float* Whh1 = (const float*)d_in[6];
    const float* bih1 = (const float*)d_in[7];
    const float* bhh1 = (const float*)d_in[8];
    const float* Wih2 = (const float*)d_in[9];
    const float* Whh2 = (const float*)d_in[10];
    const float* bih2 = (const float*)d_in[11];
    const float* bhh2 = (const float*)d_in[12];
    const float* Wfc  = (const float*)d_in[13];
    const float* bfc  = (const float*)d_in[14];
    float* out = (float*)d_out;

    static int smem_set = 0;
    if (!smem_set) {
        cudaFuncSetAttribute(lstm_step_combined, cudaFuncAttributeMaxDynamicSharedMemorySize, SMEM_DYN);
        smem_set = 1;
    }

    // one-time prep (single launch so ncu -s 5 profiles a step kernel)
    {
        dim3 pgrid((NT * NB * INP + 255) / 256, 6);
        prep_all<<<pgrid, 256>>>(x, h1, c1, h2, c2, bih1, bhh1, bih2, bhh2,
                                 Wih1, Whh1, Wih2, Whh2);
    }

    // recurrence: one combined launch per step boundary (phase0(tl) || phase1(tl-1))
    dim3 grid(G4 / 64, 1, 2);   // 128 CTAs -> 1 CTA/SM
    for (int tl = 0; tl <= NT; tl++) {
        lstm_step_combined<<<grid, 256, SMEM_DYN>>>(tl);
    }

    fc_kernel<<<dim3(NB, NC), 32>>>(Wfc, bfc, out);
}

// round 11
// speedup vs baseline: 1.8916x; 1.2687x over previous
#include <cuda_runtime.h>
#include <cuda_fp16.h>
#include <cstdint>
#include <cstddef>

// Problem dims
#define NB   128     // batch
#define NT   256     // time steps
#define HD   1024    // hidden
#define HD2  2048    // [hi|lo] row width for states
#define IN   150     // input feature (J*D)
#define INP  192     // padded input feature
#define IN2  384     // [hi|lo] row width for x
#define NC   60      // classes
#define G4   4096    // 4*HD

// GEMM tiling: CTA 128(M) x 32(N), 4 warps of 32x32, K-tile 64, 2-stage ring
#define KT      64
#define NSTAGE  2
#define AROWB   144                 // 64 fp16 (128B) + 16B pad
#define AREGB   (256 * AROWB)       // A region: Ah(128 rows) + Al(128 rows) = 36864
#define BTILEB  (32 * AROWB)        // 4608
#define STAGEB  (AREGB + BTILEB)    // 41472
#define GS_STRIDE 129
// Gs (32*129*4 = 16512 B) aliases stage buffers (free after final sync).
#define SMEM_DYN (NSTAGE * STAGEB + 128)   // 83072 -> 2 CTAs/SM

// ---------------- persistent device state ----------------
__device__ __half g_h1e[2][NB * HD2];     // [m][hi(1024)|lo(1024)]
__device__ __half g_h2e[2][NB * HD2];
__device__ float g_c1[NB * HD];
__device__ float g_c2[NB * HD];
__device__ float g_bias1e[G4];            // reordered n = u*4+g
__device__ float g_bias2e[G4];
__device__ __half g_whh1h[G4 * HD];       // fp16 weights, rows reordered n=u*4+g
__device__ __half g_wih2h[G4 * HD];
__device__ __half g_whh2h[G4 * HD];
__device__ __half g_wih1h[G4 * INP];
__device__ __half g_xe[NT * NB * IN2];    // [t][b][hi(192)|lo(192)]

// ---------------- PTX helpers ----------------
__device__ __forceinline__ uint32_t smem_u32(const void* p) {
    uint32_t a;
    asm("{ .reg .u64 t; cvta.to.shared.u64 t, %1; cvt.u32.u64 %0, t; }" : "=r"(a) : "l"(p));
    return a;
}
__device__ __forceinline__ void cpasync16(uint32_t dst, const void* src) {
    asm volatile("cp.async.cg.shared.global [%0], [%1], 16;" :: "r"(dst), "l"(src));
}
#define CP_COMMIT() asm volatile("cp.async.commit_group;" ::: "memory")
#define CP_WAIT(n)  asm volatile("cp.async.wait_group %0;" :: "n"(n) : "memory")

__device__ __forceinline__ void ldsm4(uint32_t* r, uint32_t addr) {
    asm volatile("ldmatrix.sync.aligned.m8n8.x4.shared.b16 {%0,%1,%2,%3}, [%4];"
                 : "=r"(r[0]), "=r"(r[1]), "=r"(r[2]), "=r"(r[3]) : "r"(addr));
}
__device__ __forceinline__ void mma16816(float* d, const uint32_t* a, const uint32_t* b) {
    asm volatile(
        "mma.sync.aligned.m16n8k16.row.col.f32.f16.f16.f32 "
        "{%0,%1,%2,%3}, {%4,%5,%6,%7}, {%8,%9}, {%0,%1,%2,%3};"
        : "+f"(d[0]), "+f"(d[1]), "+f"(d[2]), "+f"(d[3])
        : "r"(a[0]), "r"(a[1]), "r"(a[2]), "r"(a[3]), "r"(b[0]), "r"(b[1]));
}

__device__ __forceinline__ float sigf(float x) { return 1.0f / (1.0f + __expf(-x)); }
__device__ __forceinline__ float tanh_f(float x) { return 2.0f / (1.0f + __expf(-2.0f * x)) - 1.0f; }

// ---------------- single merged prep kernel ----------------
__device__ __forceinline__ void conv_w(const float* W, __half* out, int K, int KP, int idx) {
    if (idx >= G4 * KP) return;
    int n = idx / KP, k = idx % KP;
    int g = n & 3, u = n >> 2;
    float v = (k < K) ? W[(size_t)(g * HD + u) * K + k] : 0.0f;
    out[(size_t)n * KP + k] = __float2half(v);
}

__global__ void prep_all(const float* __restrict__ x,
                         const float* __restrict__ h1, const float* __restrict__ c1,
                         const float* __restrict__ h2, const float* __restrict__ c2,
                         const float* __restrict__ bih1, const float* __restrict__ bhh1,
                         const float* __restrict__ bih2, const float* __restrict__ bhh2,
                         const float* __restrict__ Wih1, const float* __restrict__ Whh1,
                         const float* __restrict__ Wih2, const float* __restrict__ Whh2) {
    int idx = blockIdx.x * blockDim.x + threadIdx.x;
    int task = blockIdx.y;
    if (task == 0) {
        if (idx < NB * HD) {
            int m = idx / HD, u = idx % HD;
            float v1 = h1[idx], v2 = h2[idx];
            __half h1hi = __float2half(v1);
            __half h1lo = __float2half(v1 - __half2float(h1hi));
            __half h2hi = __float2half(v2);
            __half h2lo = __float2half(v2 - __half2float(h2hi));
            size_t base = (size_t)m * HD2;
            g_h1e[0][base + u] = h1hi; g_h1e[0][base + HD + u] = h1lo;
            g_h2e[0][base + u] = h2hi; g_h2e[0][base + HD + u] = h2lo;
            g_c1[idx] = c1[idx];
            g_c2[idx] = c2[idx];
        }
        if (idx < G4) {
            int g = idx & 3, u = idx >> 2;
            int r = g * HD + u;
            g_bias1e[idx] = bih1[r] + bhh1[r];
            g_bias2e[idx] = bih2[r] + bhh2[r];
        }
    } else if (task == 1) {
        conv_w(Whh1, g_whh1h, HD, HD, idx);
    } else if (task == 2) {
        conv_w(Wih2, g_wih2h, HD, HD, idx);
    } else if (task == 3) {
        conv_w(Whh2, g_whh2h, HD, HD, idx);
    } else if (task == 4) {
        conv_w(Wih1, g_wih1h, IN, INP, idx);
    } else {
        if (idx >= NT * NB * INP) return;
        int k = idx % INP;
        int r = idx / INP;
        int b = r % NB, t = r / NB;
        float v = (k < IN) ? x[((size_t)b * NT + t) * IN + k] : 0.0f;
        __half hi = __float2half(v);
        __half lo = __float2half(v - __half2float(hi));
        size_t base = ((size_t)t * NB + b) * IN2;
        g_xe[base + k] = hi;
        g_xe[base + INP + k] = lo;
    }
}

// ---------------- combined LSTM step kernel ----------------
// tl = 0..NT.  bids 0..127  : role1 (phase1 at t=tl-1), n0 = bid*32   [skip tl==0]
//              bids 128..255: role0 (phase0 at t=tl),   n0 = (bid-128)*32 [skip tl==NT]
// Heavy role1 bids (0..107) pair with light role0 bids (148..255) on the same SM
// (classic placement maps bid and bid+148 to the same SM; 2 CTAs/SM by smem).
// block = 128 (4 warps of 32m x 32n). Per W-tile: two mma passes (Ah, Al).
__global__ void __launch_bounds__(128)
lstm_step_combined(int tl) {
    const int bid = blockIdx.x;
    int role, n0;
    if (bid < 128) { role = 1; n0 = bid * 32; if (tl == 0) return; }
    else           { role = 0; n0 = (bid - 128) * 32; if (tl == NT) return; }
    const int t = (role == 0) ? tl : (tl - 1);
    const int cur = t & 1;

    extern __shared__ __align__(16) char sm[];
    const uint32_t SB = smem_u32(sm);
    float* Gs    = (float*)sm;                       // aliases stages (after final sync)
    float* biasS = (float*)(sm + NSTAGE * STAGEB);   // 32 floats

    const int tid  = threadIdx.x;
    const int wid  = tid >> 5;
    const int lane = tid & 31;

    const __half *A0, *B0, *A1, *B1;
    const float* biasE;
    float* cst;
    __half* houtE;
    int lda1, K1, T1;
    if (role == 0) {
        A0 = g_h1e[cur];      B0 = g_whh1h;
        A1 = g_xe + (size_t)t * NB * IN2;  B1 = g_wih1h;
        lda1 = IN2; K1 = INP; T1 = INP / KT;     // 3
        biasE = g_bias1e; cst = g_c1; houtE = g_h1e[cur ^ 1];
    } else {
        A0 = g_h1e[cur ^ 1];  B0 = g_wih2h;
        A1 = g_h2e[cur];      B1 = g_whh2h;
        lda1 = HD2; K1 = HD; T1 = HD / KT;       // 16
        biasE = g_bias2e; cst = g_c2; houtE = g_h2e[cur ^ 1];
    }
    const int T0 = HD / KT;          // 16
    const int TT = T0 + T1;          // 32 or 19

    if (tid < 32) biasS[tid] = biasE[n0 + tid];

    // B loader: 32 rows x 128B, 32B per thread
    const int brow = tid >> 2;            // 0..31
    const int bcolB = (tid & 3) * 32;

    auto load_tile = [&](int tile, int stage) {
        const __half *A, *B;
        int lda, Khalf, ldb, kb;
        if (tile < T0) { A = A0; B = B0; lda = HD2;  Khalf = HD; ldb = HD; kb = tile * KT; }
        else           { A = A1; B = B1; lda = lda1; Khalf = K1; ldb = K1; kb = (tile - T0) * KT; }
        // A: thread tid loads Ah row tid and Al row tid (8 x 16B each)
        const char* ah = (const char*)(A + (size_t)tid * lda + kb);
        const char* al = (const char*)(A + (size_t)tid * lda + Khalf + kb);
        uint32_t da = SB + stage * STAGEB + tid * AROWB;
        uint32_t dl = da + 128 * AROWB;
#pragma unroll
        for (int i = 0; i < 8; i++) {
            cpasync16(da + i * 16, ah + i * 16);
            cpasync16(dl + i * 16, al + i * 16);
        }
        const char* bp = (const char*)(B + (size_t)(n0 + brow) * ldb + kb) + bcolB;
        uint32_t db = SB + stage * STAGEB + AREGB + brow * AROWB + bcolB;
        cpasync16(db,      bp);
        cpasync16(db + 16, bp + 16);
        CP_COMMIT();
    };

    // ldmatrix per-lane offsets (validated maps). Warp tile: m rows wid*32..+31, n 0..31.
    const int wr = wid;
    const int grp = lane >> 3, lr = lane & 7;
    uint32_t aoff[2], boff[2];
#pragma unroll
    for (int mi = 0; mi < 2; mi++)
        aoff[mi] = (uint32_t)((wr * 32 + mi * 16 + lr + (grp & 1) * 8) * AROWB + (grp >> 1) * 16);
#pragma unroll
    for (int nc = 0; nc < 2; nc++)
        boff[nc] = (uint32_t)((nc * 16 + lr + (grp >> 1) * 8) * AROWB + (grp & 1) * 16) + AREGB;

    float d[2][4][4];
#pragma unroll
    for (int mi = 0; mi < 2; mi++)
#pragma unroll
        for (int nj = 0; nj < 4; nj++)
#pragma unroll
            for (int q = 0; q < 4; q++) d[mi][nj][q] = 0.0f;

    // prologue
    load_tile(0, 0);
    if (TT > 1) load_tile(1, 1);

    for (int c = 0; c < TT; c++) {
        const int s = c & 1;
        if (c + 1 < TT) { CP_WAIT(1); } else { CP_WAIT(0); }
        __syncthreads();

        const uint32_t sb = SB + s * STAGEB;
#pragma unroll
        for (int kk = 0; kk < 4; kk++) {
            uint32_t ar0[4], ar1[4], b0r[4], b1r[4];
            ldsm4(b0r, sb + boff[0] + kk * 32);
            ldsm4(b1r, sb + boff[1] + kk * 32);
            // pass 1: Ah
            ldsm4(ar0, sb + aoff[0] + kk * 32);
            ldsm4(ar1, sb + aoff[1] + kk * 32);
            mma16816(d[0][0], ar0, b0r + 0);
            mma16816(d[0][1], ar0, b0r + 2);
            mma16816(d[0][2], ar0, b1r + 0);
            mma16816(d[0][3], ar0, b1r + 2);
            mma16816(d[1][0], ar1, b0r + 0);
            mma16816(d[1][1], ar1, b0r + 2);
            mma16816(d[1][2], ar1, b1r + 0);
            mma16816(d[1][3], ar1, b1r + 2);
            // pass 2: Al (B fragments reused)
            ldsm4(ar0, sb + aoff[0] + 128 * AROWB + kk * 32);
            ldsm4(ar1, sb + aoff[1] + 128 * AROWB + kk * 32);
            mma16816(d[0][0], ar0, b0r + 0);
            mma16816(d[0][1], ar0, b0r + 2);
            mma16816(d[0][2], ar0, b1r + 0);
            mma16816(d[0][3], ar0, b1r + 2);
            mma16816(d[1][0], ar1, b0r + 0);
            mma16816(d[1][1], ar1, b0r + 2);
            mma16816(d[1][2], ar1, b1r + 0);
            mma16816(d[1][3], ar1, b1r + 2);
        }
        __syncthreads();
        if (c + 2 < TT) load_tile(c + 2, s);
    }
    // no cp.async in flight; stage smem reusable as Gs

    // acc -> Gs [n][m]
#pragma unroll
    for (int mi = 0; mi < 2; mi++) {
#pragma unroll
        for (int nj = 0; nj < 4; nj++) {
            int r0 = wr * 32 + mi * 16 + (lane >> 2);
            int cb = nj * 8 + (lane & 3) * 2;
            Gs[cb * GS_STRIDE + r0]           = d[mi][nj][0];
            Gs[(cb + 1) * GS_STRIDE + r0]     = d[mi][nj][1];
            Gs[cb * GS_STRIDE + r0 + 8]       = d[mi][nj][2];
            Gs[(cb + 1) * GS_STRIDE + r0 + 8] = d[mi][nj][3];
        }
    }
    __syncthreads();

    // cell update: 128 m x 8 u = 1024 cells, 8 per thread
    const int ubase = n0 >> 2;
#pragma unroll
    for (int r = 0; r < 8; r++) {
        int idx = tid + r * 128;
        int ml = idx & 127;     // m
        int u  = idx >> 7;      // 0..7
        int nb = u * 4;
        float gi_ = Gs[(nb + 0) * GS_STRIDE + ml] + biasS[nb + 0];
        float gf_ = Gs[(nb + 1) * GS_STRIDE + ml] + biasS[nb + 1];
        float gg_ = Gs[(nb + 2) * GS_STRIDE + ml] + biasS[nb + 2];
        float go_ = Gs[(nb + 3) * GS_STRIDE + ml] + biasS[nb + 3];
        int ug = ubase + u;
        int off = ml * HD + ug;
        float cv = cst[off];
        float cn = sigf(gf_) * cv + sigf(gi_) * tanh_f(gg_);
        cst[off] = cn;
        float h = sigf(go_) * tanh_f(cn);
        __half hi = __float2half(h);
        __half lo = __float2half(h - __half2float(hi));
        size_t hb = (size_t)ml * HD2;
        houtE[hb + ug] = hi;
        houtE[hb + HD + ug] = lo;
    }
}

// ---------------- final FC: out = h2 @ Wfc^T + bfc ----------------
__global__ void fc_kernel(const float* __restrict__ Wfc, const float* __restrict__ bfc,
                          float* __restrict__ out) {
    int b = blockIdx.x;
    int c = blockIdx.y;
    int lane = threadIdx.x;
    // last phase1 (t=NT-1, odd) wrote g_h2e[0]
    const __half* he = &g_h2e[0][(size_t)b * HD2];
    const float* w = Wfc + (size_t)c * HD;
    float s = 0.0f;
    for (int k = lane; k < HD; k += 32) {
        float h = __half2float(he[k]) + __half2float(he[HD + k]);
        s += h * w[k];
    }
#pragma unroll
    for (int o = 16; o > 0; o >>= 1) s += __shfl_xor_sync(0xFFFFFFFFu, s, o);
    if (lane == 0) out[b * NC + c] = s + bfc[c];
}

// ---------------- launch ----------------
extern "C" void kernel_launch(void* const* d_in, const int* in_sizes, int n_in,
                              void* d_out, int out_size) {
    (void)in_sizes; (void)n_in; (void)out_size;
    const float* x    = (const float*)d_in[0];
    const float* h1   = (const float*)d_in[1];
    const float* c1   = (const float*)d_in[2];
    const float* h2   = (const float*)d_in[3];
    const float* c2   = (const float*)d_in[4];
    const float* Wih1 = (const float*)d_in[5];
    const float* Whh1 = (const float*)d_in[6];
    const float* bih1 = (const float*)d_in[7];
    const float* bhh1 = (const float*)d_in[8];
    const float* Wih2 = (const float*)d_in[9];
    const float* Whh2 = (const float*)d_in[10];
    const float* bih2 = (const float*)d_in[11];
    const float* bhh2 = (const float*)d_in[12];
    const float* Wfc  = (const float*)d_in[13];
    const float* bfc  = (const float*)d_in[14];
    float* out = (float*)d_out;

    static int smem_set = 0;
    if (!smem_set) {
        cudaFuncSetAttribute(lstm_step_combined, cudaFuncAttributeMaxDynamicSharedMemorySize, SMEM_DYN);
        smem_set = 1;
    }

    // one-time prep (single launch)
    {
        dim3 pgrid((NT * NB * INP + 255) / 256, 6);
        prep_all<<<pgrid, 256>>>(x, h1, c1, h2, c2, bih1, bhh1, bih2, bhh2,
                                 Wih1, Whh1, Wih2, Whh2);
    }

    // recurrence: one combined launch per step boundary
    for (int tl = 0; tl <= NT; tl++) {
        lstm_step_combined<<<256, 128, SMEM_DYN>>>(tl);
    }

    fc_kernel<<<dim3(NB, NC), 32>>>(Wfc, bfc, out);
}

// round 12
// speedup vs baseline: 2.2940x; 1.2127x over previous
#include <cuda_runtime.h>
#include <cuda_fp16.h>
#include <cstdint>
#include <cstddef>

// Problem dims
#define NB   128     // batch
#define NT   256     // time steps
#define HD   1024    // hidden
#define HD2  2048    // [hi|lo] row width for states
#define IN   150     // input feature (J*D)
#define INP  192     // padded input feature
#define IN2  384     // [hi|lo] row width for x
#define NC   60      // classes
#define G4   4096    // 4*HD

// GEMM tiling: CTA 128(M) x 64(N), 8 warps of 32x32, K-tile 64, 4-stage ring
#define KT      64
#define NSTAGE  4
#define AROWB   144                 // 64 fp16 (128B) + 16B pad
#define AREGB   (256 * AROWB)       // Ah(128 rows) + Al(128 rows) = 36864
#define BTILEB  (64 * AROWB)        // 9216
#define STAGEB  (AREGB + BTILEB)    // 46080
#define GS_STRIDE 129
// Gs (64*129*4 = 33024 B) aliases stage buffers (free after final sync).
#define SMEM_DYN (NSTAGE * STAGEB + 256)   // 184576 -> 1 CTA/SM

// ---------------- persistent device state ----------------
__device__ __half g_h1e[2][NB * HD2];     // [m][hi(1024)|lo(1024)]
__device__ __half g_h2e[2][NB * HD2];
__device__ float g_c1[NB * HD];
__device__ float g_c2[NB * HD];
__device__ float g_bias1e[G4];            // reordered n = u*4+g
__device__ float g_bias2e[G4];
__device__ __half g_whh1h[G4 * HD];       // fp16 weights, rows reordered n=u*4+g
__device__ __half g_wih2h[G4 * HD];
__device__ __half g_whh2h[G4 * HD];
__device__ __half g_wih1h[G4 * INP];
__device__ __half g_xe[NT * NB * IN2];    // [t][b][hi(192)|lo(192)]

// ---------------- PTX helpers ----------------
__device__ __forceinline__ uint32_t smem_u32(const void* p) {
    uint32_t a;
    asm("{ .reg .u64 t; cvta.to.shared.u64 t, %1; cvt.u32.u64 %0, t; }" : "=r"(a) : "l"(p));
    return a;
}
__device__ __forceinline__ void cpasync16(uint32_t dst, const void* src) {
    asm volatile("cp.async.cg.shared.global [%0], [%1], 16;" :: "r"(dst), "l"(src));
}
#define CP_COMMIT() asm volatile("cp.async.commit_group;" ::: "memory")
#define CP_WAIT(n)  asm volatile("cp.async.wait_group %0;" :: "n"(n) : "memory")

__device__ __forceinline__ void ldsm4(uint32_t* r, uint32_t addr) {
    asm volatile("ldmatrix.sync.aligned.m8n8.x4.shared.b16 {%0,%1,%2,%3}, [%4];"
                 : "=r"(r[0]), "=r"(r[1]), "=r"(r[2]), "=r"(r[3]) : "r"(addr));
}
__device__ __forceinline__ void mma16816(float* d, const uint32_t* a, const uint32_t* b) {
    asm volatile(
        "mma.sync.aligned.m16n8k16.row.col.f32.f16.f16.f32 "
        "{%0,%1,%2,%3}, {%4,%5,%6,%7}, {%8,%9}, {%0,%1,%2,%3};"
        : "+f"(d[0]), "+f"(d[1]), "+f"(d[2]), "+f"(d[3])
        : "r"(a[0]), "r"(a[1]), "r"(a[2]), "r"(a[3]), "r"(b[0]), "r"(b[1]));
}

__device__ __forceinline__ float sigf(float x) { return 1.0f / (1.0f + __expf(-x)); }
__device__ __forceinline__ float tanh_f(float x) { return 2.0f / (1.0f + __expf(-2.0f * x)) - 1.0f; }

// ---------------- single merged prep kernel ----------------
__device__ __forceinline__ void conv_w(const float* W, __half* out, int K, int KP, int idx) {
    if (idx >= G4 * KP) return;
    int n = idx / KP, k = idx % KP;
    int g = n & 3, u = n >> 2;
    float v = (k < K) ? W[(size_t)(g * HD + u) * K + k] : 0.0f;
    out[(size_t)n * KP + k] = __float2half(v);
}

__global__ void prep_all(const float* __restrict__ x,
                         const float* __restrict__ h1, const float* __restrict__ c1,
                         const float* __restrict__ h2, const float* __restrict__ c2,
                         const float* __restrict__ bih1, const float* __restrict__ bhh1,
                         const float* __restrict__ bih2, const float* __restrict__ bhh2,
                         const float* __restrict__ Wih1, const float* __restrict__ Whh1,
                         const float* __restrict__ Wih2, const float* __restrict__ Whh2) {
    int idx = blockIdx.x * blockDim.x + threadIdx.x;
    int task = blockIdx.y;
    if (task == 0) {
        if (idx < NB * HD) {
            int m = idx / HD, u = idx % HD;
            float v1 = h1[idx], v2 = h2[idx];
            __half h1hi = __float2half(v1);
            __half h1lo = __float2half(v1 - __half2float(h1hi));
            __half h2hi = __float2half(v2);
            __half h2lo = __float2half(v2 - __half2float(h2hi));
            size_t base = (size_t)m * HD2;
            g_h1e[0][base + u] = h1hi; g_h1e[0][base + HD + u] = h1lo;
            g_h2e[0][base + u] = h2hi; g_h2e[0][base + HD + u] = h2lo;
            g_c1[idx] = c1[idx];
            g_c2[idx] = c2[idx];
        }
        if (idx < G4) {
            int g = idx & 3, u = idx >> 2;
            int r = g * HD + u;
            g_bias1e[idx] = bih1[r] + bhh1[r];
            g_bias2e[idx] = bih2[r] + bhh2[r];
        }
    } else if (task == 1) {
        conv_w(Whh1, g_whh1h, HD, HD, idx);
    } else if (task == 2) {
        conv_w(Wih2, g_wih2h, HD, HD, idx);
    } else if (task == 3) {
        conv_w(Whh2, g_whh2h, HD, HD, idx);
    } else if (task == 4) {
        conv_w(Wih1, g_wih1h, IN, INP, idx);
    } else {
        if (idx >= NT * NB * INP) return;
        int k = idx % INP;
        int r = idx / INP;
        int b = r % NB, t = r / NB;
        float v = (k < IN) ? x[((size_t)b * NT + t) * IN + k] : 0.0f;
        __half hi = __float2half(v);
        __half lo = __float2half(v - __half2float(hi));
        size_t base = ((size_t)t * NB + b) * IN2;
        g_xe[base + k] = hi;
        g_xe[base + INP + k] = lo;
    }
}

// ---------------- combined LSTM step kernel ----------------
// tl = 0..NT.  blockIdx.z==1: role1 (phase1 at t=tl-1)  [skip tl==0]
//              blockIdx.z==0: role0 (phase0 at t=tl)    [skip tl==NT]
// grid = (64 n-tiles, 1, 2 roles) = 128 CTAs, 1 per SM, roles on disjoint SMs.
// block = 256 (8 warps): warp tile 32x32 (m-quarter wid>>1, n-half wid&1).
// Per W-tile: two mma passes (Ah, Al), B fragments reused.
__global__ void __launch_bounds__(256)
lstm_step_combined(int tl) {
    const int role = blockIdx.z;
    if (role == 0 && tl == NT) return;
    if (role == 1 && tl == 0) return;
    const int t = (role == 0) ? tl : (tl - 1);
    const int cur = t & 1;
    const int n0 = blockIdx.x * 64;

    extern __shared__ __align__(16) char sm[];
    const uint32_t SB = smem_u32(sm);
    float* Gs    = (float*)sm;                       // aliases stages (after final sync)
    float* biasS = (float*)(sm + NSTAGE * STAGEB);   // 64 floats

    const int tid  = threadIdx.x;
    const int wid  = tid >> 5;
    const int lane = tid & 31;

    const __half *A0, *B0, *A1, *B1;
    const float* biasE;
    float* cst;
    __half* houtE;
    int lda1, K1, T1;
    if (role == 0) {
        A0 = g_h1e[cur];      B0 = g_whh1h;
        A1 = g_xe + (size_t)t * NB * IN2;  B1 = g_wih1h;
        lda1 = IN2; K1 = INP; T1 = INP / KT;     // 3
        biasE = g_bias1e; cst = g_c1; houtE = g_h1e[cur ^ 1];
    } else {
        A0 = g_h1e[cur ^ 1];  B0 = g_wih2h;
        A1 = g_h2e[cur];      B1 = g_whh2h;
        lda1 = HD2; K1 = HD; T1 = HD / KT;       // 16
        biasE = g_bias2e; cst = g_c2; houtE = g_h2e[cur ^ 1];
    }
    const int T0 = HD / KT;          // 16
    const int TT = T0 + T1;          // 32 or 19

    float biasR = (tid < 64) ? biasE[n0 + tid] : 0.0f;

    // loaders: A 128 rows (hi) + 128 rows (lo), half-row 64B per thread (4x16B each);
    //          B 64 rows, quarter-row 32B per thread (2x16B)
    const int arow = tid >> 1;            // 0..127
    const int acolB = (tid & 1) * 64;
    const int brow = tid >> 2;            // 0..63
    const int bcolB = (tid & 3) * 32;

    auto load_tile = [&](int tile, int stage) {
        const __half *A, *B;
        int lda, Khalf, ldb, kb;
        if (tile < T0) { A = A0; B = B0; lda = HD2;  Khalf = HD; ldb = HD; kb = tile * KT; }
        else           { A = A1; B = B1; lda = lda1; Khalf = K1; ldb = K1; kb = (tile - T0) * KT; }
        const char* ah = (const char*)(A + (size_t)arow * lda + kb) + acolB;
        const char* al = (const char*)(A + (size_t)arow * lda + Khalf + kb) + acolB;
        uint32_t da = SB + stage * STAGEB + arow * AROWB + acolB;
        uint32_t dl = da + 128 * AROWB;
#pragma unroll
        for (int i = 0; i < 4; i++) {
            cpasync16(da + i * 16, ah + i * 16);
            cpasync16(dl + i * 16, al + i * 16);
        }
        const char* bp = (const char*)(B + (size_t)(n0 + brow) * ldb + kb) + bcolB;
        uint32_t db = SB + stage * STAGEB + AREGB + brow * AROWB + bcolB;
        cpasync16(db,      bp);
        cpasync16(db + 16, bp + 16);
        CP_COMMIT();
    };

    // ldmatrix per-lane offsets (R10-validated maps)
    const int wr = wid >> 1;      // m quarter (0..3)
    const int wc = wid & 1;       // n half
    const int grp = lane >> 3, lr = lane & 7;
    uint32_t aoff[2], boff[2];
#pragma unroll
    for (int mi = 0; mi < 2; mi++)
        aoff[mi] = (uint32_t)((wr * 32 + mi * 16 + lr + (grp & 1) * 8) * AROWB + (grp >> 1) * 16);
#pragma unroll
    for (int nc = 0; nc < 2; nc++)
        boff[nc] = (uint32_t)((wc * 32 + nc * 16 + lr + (grp >> 1) * 8) * AROWB + (grp & 1) * 16) + AREGB;

    float d[2][4][4];
#pragma unroll
    for (int mi = 0; mi < 2; mi++)
#pragma unroll
        for (int nj = 0; nj < 4; nj++)
#pragma unroll
            for (int q = 0; q < 4; q++) d[mi][nj][q] = 0.0f;

    // prologue: 3 stages in flight
    load_tile(0, 0);
    load_tile(1, 1);
    load_tile(2, 2);

    for (int c = 0; c < TT; c++) {
        const int s = c & (NSTAGE - 1);
        if (c < TT - 2)       { CP_WAIT(2); }
        else if (c == TT - 2) { CP_WAIT(1); }
        else                  { CP_WAIT(0); }
        __syncthreads();
        if (c + 3 < TT) load_tile(c + 3, (c + 3) & (NSTAGE - 1));

        const uint32_t sb = SB + s * STAGEB;
#pragma unroll
        for (int kk = 0; kk < 4; kk++) {
            uint32_t ar0[4], ar1[4], b0r[4], b1r[4];
            ldsm4(b0r, sb + boff[0] + kk * 32);
            ldsm4(b1r, sb + boff[1] + kk * 32);
            // pass 1: Ah
            ldsm4(ar0, sb + aoff[0] + kk * 32);
            ldsm4(ar1, sb + aoff[1] + kk * 32);
            mma16816(d[0][0], ar0, b0r + 0);
            mma16816(d[0][1], ar0, b0r + 2);
            mma16816(d[0][2], ar0, b1r + 0);
            mma16816(d[0][3], ar0, b1r + 2);
            mma16816(d[1][0], ar1, b0r + 0);
            mma16816(d[1][1], ar1, b0r + 2);
            mma16816(d[1][2], ar1, b1r + 0);
            mma16816(d[1][3], ar1, b1r + 2);
            // pass 2: Al (B fragments reused)
            ldsm4(ar0, sb + aoff[0] + 128 * AROWB + kk * 32);
            ldsm4(ar1, sb + aoff[1] + 128 * AROWB + kk * 32);
            mma16816(d[0][0], ar0, b0r + 0);
            mma16816(d[0][1], ar0, b0r + 2);
            mma16816(d[0][2], ar0, b1r + 0);
            mma16816(d[0][3], ar0, b1r + 2);
            mma16816(d[1][0], ar1, b0r + 0);
            mma16816(d[1][1], ar1, b0r + 2);
            mma16816(d[1][2], ar1, b1r + 0);
            mma16816(d[1][3], ar1, b1r + 2);
        }
    }
    __syncthreads();   // all ldsm reads done; stage smem now reusable as Gs

    if (tid < 64) biasS[tid] = biasR;

    // acc -> Gs [n][m]
#pragma unroll
    for (int mi = 0; mi < 2; mi++) {
#pragma unroll
        for (int nj = 0; nj < 4; nj++) {
            int r0 = wr * 32 + mi * 16 + (lane >> 2);
            int cb = wc * 32 + nj * 8 + (lane & 3) * 2;
            Gs[cb * GS_STRIDE + r0]           = d[mi][nj][0];
            Gs[(cb + 1) * GS_STRIDE + r0]     = d[mi][nj][1];
            Gs[cb * GS_STRIDE + r0 + 8]       = d[mi][nj][2];
            Gs[(cb + 1) * GS_STRIDE + r0 + 8] = d[mi][nj][3];
        }
    }
    __syncthreads();

    // cell update: 128 m x 16 u = 2048 cells, 8 per thread
    const int ubase = n0 >> 2;
#pragma unroll
    for (int r = 0; r < 8; r++) {
        int idx = tid + r * 256;
        int ml = idx & 127;     // m
        int u  = idx >> 7;      // 0..15
        int nb = u * 4;
        float gi_ = Gs[(nb + 0) * GS_STRIDE + ml] + biasS[nb + 0];
        float gf_ = Gs[(nb + 1) * GS_STRIDE + ml] + biasS[nb + 1];
        float gg_ = Gs[(nb + 2) * GS_STRIDE + ml] + biasS[nb + 2];
        float go_ = Gs[(nb + 3) * GS_STRIDE + ml] + biasS[nb + 3];
        int ug = ubase + u;
        int off = ml * HD + ug;
        float cv = cst[off];
        float cn = sigf(gf_) * cv + sigf(gi_) * tanh_f(gg_);
        cst[off] = cn;
        float h = sigf(go_) * tanh_f(cn);
        __half hi = __float2half(h);
        __half lo = __float2half(h - __half2float(hi));
        size_t hb = (size_t)ml * HD2;
        houtE[hb + ug] = hi;
        houtE[hb + HD + ug] = lo;
    }
}

// ---------------- final FC: out = h2 @ Wfc^T + bfc ----------------
__global__ void fc_kernel(const float* __restrict__ Wfc, const float* __restrict__ bfc,
                          float* __restrict__ out) {
    int b = blockIdx.x;
    int c = blockIdx.y;
    int lane = threadIdx.x;
    // last phase1 (t=NT-1, odd) wrote g_h2e[0]
    const __half* he = &g_h2e[0][(size_t)b * HD2];
    const float* w = Wfc + (size_t)c * HD;
    float s = 0.0f;
    for (int k = lane; k < HD; k += 32) {
        float h = __half2float(he[k]) + __half2float(he[HD + k]);
        s += h * w[k];
    }
#pragma unroll
    for (int o = 16; o > 0; o >>= 1) s += __shfl_xor_sync(0xFFFFFFFFu, s, o);
    if (lane == 0) out[b * NC + c] = s + bfc[c];
}

// ---------------- launch ----------------
extern "C" void kernel_launch(void* const* d_in, const int* in_sizes, int n_in,
                              void* d_out, int out_size) {
    (void)in_sizes; (void)n_in; (void)out_size;
    const float* x    = (const float*)d_in[0];
    const float* h1   = (const float*)d_in[1];
    const float* c1   = (const float*)d_in[2];
    const float* h2   = (const float*)d_in[3];
    const float* c2   = (const float*)d_in[4];
    const float* Wih1 = (const float*)d_in[5];
    const float* Whh1 = (const float*)d_in[6];
    const float* bih1 = (const float*)d_in[7];
    const float* bhh1 = (const float*)d_in[8];
    const float* Wih2 = (const float*)d_in[9];
    const float* Whh2 = (const float*)d_in[10];
    const float* bih2 = (const float*)d_in[11];
    const float* bhh2 = (const float*)d_in[12];
    const float* Wfc  = (const float*)d_in[13];
    const float* bfc  = (const float*)d_in[14];
    float* out = (float*)d_out;

    static int smem_set = 0;
    if (!smem_set) {
        cudaFuncSetAttribute(lstm_step_combined, cudaFuncAttributeMaxDynamicSharedMemorySize, SMEM_DYN);
        smem_set = 1;
    }

    // one-time prep (single launch)
    {
        dim3 pgrid((NT * NB * INP + 255) / 256, 6);
        prep_all<<<pgrid, 256>>>(x, h1, c1, h2, c2, bih1, bhh1, bih2, bhh2,
                                 Wih1, Whh1, Wih2, Whh2);
    }

    // recurrence: one combined launch per step boundary
    dim3 grid(G4 / 64, 1, 2);   // 128 CTAs
    for (int tl = 0; tl <= NT; tl++) {
        lstm_step_combined<<<grid, 256, SMEM_DYN>>>(tl);
    }

    fc_kernel<<<dim3(NB, NC), 32>>>(Wfc, bfc, out);
}

// round 13
// speedup vs baseline: 2.3152x; 1.0092x over previous
#include <cuda_runtime.h>
#include <cuda_fp16.h>
#include <cstdint>
#include <cstddef>

// Problem dims
#define NB   128     // batch
#define NT   256     // time steps
#define HD   1024    // hidden
#define HD2  2048    // [hi|lo] row width for states
#define IN   150     // input feature (J*D)
#define INP  192     // padded input feature
#define IN2  384     // [hi|lo] row width for x
#define NC   60      // classes
#define G4   4096    // 4*HD

// GEMM tiling: CTA 128(M) x 64(N), 16 warps of 16x32, K-tile 64, 4-stage ring
#define KT      64
#define NSTAGE  4
#define AROWB   144                 // 64 fp16 (128B) + 16B pad
#define AREGB   (256 * AROWB)       // Ah(128 rows) + Al(128 rows) = 36864
#define BTILEB  (64 * AROWB)        // 9216
#define STAGEB  (AREGB + BTILEB)    // 46080
#define GS_STRIDE 129
// Gs (64*129*4 = 33024 B) aliases stage buffers (free after final sync).
#define SMEM_DYN (NSTAGE * STAGEB + 256)   // 184576 -> 1 CTA/SM

// ---------------- persistent device state ----------------
__device__ __half g_h1e[2][NB * HD2];     // [m][hi(1024)|lo(1024)]
__device__ __half g_h2e[2][NB * HD2];
__device__ float g_c1[NB * HD];
__device__ float g_c2[NB * HD];
__device__ float g_bias1e[G4];            // reordered n = u*4+g
__device__ float g_bias2e[G4];
__device__ __half g_whh1h[G4 * HD];       // fp16 weights, rows reordered n=u*4+g
__device__ __half g_wih2h[G4 * HD];
__device__ __half g_whh2h[G4 * HD];
__device__ __half g_wih1h[G4 * INP];
__device__ __half g_xe[NT * NB * IN2];    // [t][b][hi(192)|lo(192)]

// ---------------- PTX helpers ----------------
__device__ __forceinline__ uint32_t smem_u32(const void* p) {
    uint32_t a;
    asm("{ .reg .u64 t; cvta.to.shared.u64 t, %1; cvt.u32.u64 %0, t; }" : "=r"(a) : "l"(p));
    return a;
}
__device__ __forceinline__ void cpasync16(uint32_t dst, const void* src) {
    asm volatile("cp.async.cg.shared.global [%0], [%1], 16;" :: "r"(dst), "l"(src));
}
#define CP_COMMIT() asm volatile("cp.async.commit_group;" ::: "memory")
#define CP_WAIT(n)  asm volatile("cp.async.wait_group %0;" :: "n"(n) : "memory")

__device__ __forceinline__ void ldsm4(uint32_t* r, uint32_t addr) {
    asm volatile("ldmatrix.sync.aligned.m8n8.x4.shared.b16 {%0,%1,%2,%3}, [%4];"
                 : "=r"(r[0]), "=r"(r[1]), "=r"(r[2]), "=r"(r[3]) : "r"(addr));
}
__device__ __forceinline__ void mma16816(float* d, const uint32_t* a, const uint32_t* b) {
    asm volatile(
        "mma.sync.aligned.m16n8k16.row.col.f32.f16.f16.f32 "
        "{%0,%1,%2,%3}, {%4,%5,%6,%7}, {%8,%9}, {%0,%1,%2,%3};"
        : "+f"(d[0]), "+f"(d[1]), "+f"(d[2]), "+f"(d[3])
        : "r"(a[0]), "r"(a[1]), "r"(a[2]), "r"(a[3]), "r"(b[0]), "r"(b[1]));
}

__device__ __forceinline__ float sigf(float x) { return 1.0f / (1.0f + __expf(-x)); }
__device__ __forceinline__ float tanh_f(float x) { return 2.0f / (1.0f + __expf(-2.0f * x)) - 1.0f; }

// ---------------- single merged prep kernel ----------------
__device__ __forceinline__ void conv_w(const float* W, __half* out, int K, int KP, int idx) {
    if (idx >= G4 * KP) return;
    int n = idx / KP, k = idx % KP;
    int g = n & 3, u = n >> 2;
    float v = (k < K) ? W[(size_t)(g * HD + u) * K + k] : 0.0f;
    out[(size_t)n * KP + k] = __float2half(v);
}

__global__ void prep_all(const float* __restrict__ x,
                         const float* __restrict__ h1, const float* __restrict__ c1,
                         const float* __restrict__ h2, const float* __restrict__ c2,
                         const float* __restrict__ bih1, const float* __restrict__ bhh1,
                         const float* __restrict__ bih2, const float* __restrict__ bhh2,
                         const float* __restrict__ Wih1, const float* __restrict__ Whh1,
                         const float* __restrict__ Wih2, const float* __restrict__ Whh2) {
    int idx = blockIdx.x * blockDim.x + threadIdx.x;
    int task = blockIdx.y;
    if (task == 0) {
        if (idx < NB * HD) {
            int m = idx / HD, u = idx % HD;
            float v1 = h1[idx], v2 = h2[idx];
            __half h1hi = __float2half(v1);
            __half h1lo = __float2half(v1 - __half2float(h1hi));
            __half h2hi = __float2half(v2);
            __half h2lo = __float2half(v2 - __half2float(h2hi));
            size_t base = (size_t)m * HD2;
            g_h1e[0][base + u] = h1hi; g_h1e[0][base + HD + u] = h1lo;
            g_h2e[0][base + u] = h2hi; g_h2e[0][base + HD + u] = h2lo;
            g_c1[idx] = c1[idx];
            g_c2[idx] = c2[idx];
        }
        if (idx < G4) {
            int g = idx & 3, u = idx >> 2;
            int r = g * HD + u;
            g_bias1e[idx] = bih1[r] + bhh1[r];
            g_bias2e[idx] = bih2[r] + bhh2[r];
        }
    } else if (task == 1) {
        conv_w(Whh1, g_whh1h, HD, HD, idx);
    } else if (task == 2) {
        conv_w(Wih2, g_wih2h, HD, HD, idx);
    } else if (task == 3) {
        conv_w(Whh2, g_whh2h, HD, HD, idx);
    } else if (task == 4) {
        conv_w(Wih1, g_wih1h, IN, INP, idx);
    } else {
        if (idx >= NT * NB * INP) return;
        int k = idx % INP;
        int r = idx / INP;
        int b = r % NB, t = r / NB;
        float v = (k < IN) ? x[((size_t)b * NT + t) * IN + k] : 0.0f;
        __half hi = __float2half(v);
        __half lo = __float2half(v - __half2float(hi));
        size_t base = ((size_t)t * NB + b) * IN2;
        g_xe[base + k] = hi;
        g_xe[base + INP + k] = lo;
    }
}

// ---------------- combined LSTM step kernel ----------------
// tl = 0..NT.  blockIdx.z==1: role1 (phase1 at t=tl-1)  [skip tl==0]
//              blockIdx.z==0: role0 (phase0 at t=tl)    [skip tl==NT]
// grid = (64 n-tiles, 1, 2 roles) = 128 CTAs, 1 per SM, roles on disjoint SMs.
// block = 512 (16 warps): warp tile 16m x 32n (m-eighth wid>>1, n-half wid&1).
// Per W-tile: two mma passes (Ah, Al), B fragments reused.
__global__ void __launch_bounds__(512)
lstm_step_combined(int tl) {
    const int role = blockIdx.z;
    if (role == 0 && tl == NT) return;
    if (role == 1 && tl == 0) return;
    const int t = (role == 0) ? tl : (tl - 1);
    const int cur = t & 1;
    const int n0 = blockIdx.x * 64;

    extern __shared__ __align__(16) char sm[];
    const uint32_t SB = smem_u32(sm);
    float* Gs    = (float*)sm;                       // aliases stages (after final sync)
    float* biasS = (float*)(sm + NSTAGE * STAGEB);   // 64 floats

    const int tid  = threadIdx.x;
    const int wid  = tid >> 5;
    const int lane = tid & 31;

    const __half *A0, *B0, *A1, *B1;
    const float* biasE;
    float* cst;
    __half* houtE;
    int lda1, K1, T1;
    if (role == 0) {
        A0 = g_h1e[cur];      B0 = g_whh1h;
        A1 = g_xe + (size_t)t * NB * IN2;  B1 = g_wih1h;
        lda1 = IN2; K1 = INP; T1 = INP / KT;     // 3
        biasE = g_bias1e; cst = g_c1; houtE = g_h1e[cur ^ 1];
    } else {
        A0 = g_h1e[cur ^ 1];  B0 = g_wih2h;
        A1 = g_h2e[cur];      B1 = g_whh2h;
        lda1 = HD2; K1 = HD; T1 = HD / KT;       // 16
        biasE = g_bias2e; cst = g_c2; houtE = g_h2e[cur ^ 1];
    }
    const int T0 = HD / KT;          // 16
    const int TT = T0 + T1;          // 32 or 19

    float biasR = (tid < 64) ? biasE[n0 + tid] : 0.0f;

    // loaders (512 threads):
    //   A region: 256 rows (Ah 0-127, Al 128-255) x 128B; thread -> row tid>>1,
    //   64B half-row, 4 x 16B.
    //   B: 64 rows x 128B; thread -> row tid>>3, 16B chunk (tid&7)*16.
    const int arow2 = tid >> 1;            // 0..255
    const int arowm = arow2 & 127;         // source row
    const int ahalf = arow2 >> 7;          // 0 = hi, 1 = lo
    const int acolB = (tid & 1) * 64;
    const int brow = tid >> 3;             // 0..63
    const int bcolB = (tid & 7) * 16;

    auto load_tile = [&](int tile, int stage) {
        const __half *A, *B;
        int lda, Khalf, ldb, kb;
        if (tile < T0) { A = A0; B = B0; lda = HD2;  Khalf = HD; ldb = HD; kb = tile * KT; }
        else           { A = A1; B = B1; lda = lda1; Khalf = K1; ldb = K1; kb = (tile - T0) * KT; }
        const char* ap = (const char*)(A + (size_t)arowm * lda + (ahalf ? Khalf : 0) + kb) + acolB;
        uint32_t da = SB + stage * STAGEB + arow2 * AROWB + acolB;
#pragma unroll
        for (int i = 0; i < 4; i++) cpasync16(da + i * 16, ap + i * 16);
        const char* bp = (const char*)(B + (size_t)(n0 + brow) * ldb + kb) + bcolB;
        uint32_t db = SB + stage * STAGEB + AREGB + brow * AROWB + bcolB;
        cpasync16(db, bp);
        CP_COMMIT();
    };

    // ldmatrix per-lane offsets (validated maps, warp tile 16m x 32n)
    const int wr = wid >> 1;      // m eighth (0..7), rows wr*16..+15
    const int wc = wid & 1;       // n half
    const int grp = lane >> 3, lr = lane & 7;
    const uint32_t aoffH =
        (uint32_t)((wr * 16 + lr + (grp & 1) * 8) * AROWB + (grp >> 1) * 16);
    const uint32_t aoffL = aoffH + 128 * AROWB;
    uint32_t boff[2];
#pragma unroll
    for (int nc = 0; nc < 2; nc++)
        boff[nc] = (uint32_t)((wc * 32 + nc * 16 + lr + (grp >> 1) * 8) * AROWB + (grp & 1) * 16) + AREGB;

    float d[4][4];
#pragma unroll
    for (int nj = 0; nj < 4; nj++)
#pragma unroll
        for (int q = 0; q < 4; q++) d[nj][q] = 0.0f;

    // prologue: 3 stages in flight
    load_tile(0, 0);
    load_tile(1, 1);
    load_tile(2, 2);

    for (int c = 0; c < TT; c++) {
        const int s = c & (NSTAGE - 1);
        if (c < TT - 2)       { CP_WAIT(2); }
        else if (c == TT - 2) { CP_WAIT(1); }
        else                  { CP_WAIT(0); }
        __syncthreads();
        if (c + 3 < TT) load_tile(c + 3, (c + 3) & (NSTAGE - 1));

        const uint32_t sb = SB + s * STAGEB;
#pragma unroll
        for (int kk = 0; kk < 4; kk++) {
            uint32_t ah[4], al[4], b0r[4], b1r[4];
            ldsm4(b0r, sb + boff[0] + kk * 32);
            ldsm4(b1r, sb + boff[1] + kk * 32);
            ldsm4(ah,  sb + aoffH   + kk * 32);
            ldsm4(al,  sb + aoffL   + kk * 32);
            // pass 1: Ah
            mma16816(d[0], ah, b0r + 0);
            mma16816(d[1], ah, b0r + 2);
            mma16816(d[2], ah, b1r + 0);
            mma16816(d[3], ah, b1r + 2);
            // pass 2: Al (B fragments reused)
            mma16816(d[0], al, b0r + 0);
            mma16816(d[1], al, b0r + 2);
            mma16816(d[2], al, b1r + 0);
            mma16816(d[3], al, b1r + 2);
        }
    }
    __syncthreads();   // all ldsm reads done; stage smem now reusable as Gs

    if (tid < 64) biasS[tid] = biasR;

    // acc -> Gs [n][m]
#pragma unroll
    for (int nj = 0; nj < 4; nj++) {
        int r0 = wr * 16 + (lane >> 2);
        int cb = wc * 32 + nj * 8 + (lane & 3) * 2;
        Gs[cb * GS_STRIDE + r0]           = d[nj][0];
        Gs[(cb + 1) * GS_STRIDE + r0]     = d[nj][1];
        Gs[cb * GS_STRIDE + r0 + 8]       = d[nj][2];
        Gs[(cb + 1) * GS_STRIDE + r0 + 8] = d[nj][3];
    }
    __syncthreads();

    // cell update: 128 m x 16 u = 2048 cells, 4 per thread
    const int ubase = n0 >> 2;
#pragma unroll
    for (int r = 0; r < 4; r++) {
        int idx = tid + r * 512;
        int ml = idx & 127;     // m
        int u  = idx >> 7;      // 0..15
        int nb = u * 4;
        float gi_ = Gs[(nb + 0) * GS_STRIDE + ml] + biasS[nb + 0];
        float gf_ = Gs[(nb + 1) * GS_STRIDE + ml] + biasS[nb + 1];
        float gg_ = Gs[(nb + 2) * GS_STRIDE + ml] + biasS[nb + 2];
        float go_ = Gs[(nb + 3) * GS_STRIDE + ml] + biasS[nb + 3];
        int ug = ubase + u;
        int off = ml * HD + ug;
        float cv = cst[off];
        float cn = sigf(gf_) * cv + sigf(gi_) * tanh_f(gg_);
        cst[off] = cn;
        float h = sigf(go_) * tanh_f(cn);
        __half hi = __float2half(h);
        __half lo = __float2half(h - __half2float(hi));
        size_t hb = (size_t)ml * HD2;
        houtE[hb + ug] = hi;
        houtE[hb + HD + ug] = lo;
    }
}

// ---------------- final FC: out = h2 @ Wfc^T + bfc ----------------
__global__ void fc_kernel(const float* __restrict__ Wfc, const float* __restrict__ bfc,
                          float* __restrict__ out) {
    int b = blockIdx.x;
    int c = blockIdx.y;
    int lane = threadIdx.x;
    // last phase1 (t=NT-1, odd) wrote g_h2e[0]
    const __half* he = &g_h2e[0][(size_t)b * HD2];
    const float* w = Wfc + (size_t)c * HD;
    float s = 0.0f;
    for (int k = lane; k < HD; k += 32) {
        float h = __half2float(he[k]) + __half2float(he[HD + k]);
        s += h * w[k];
    }
#pragma unroll
    for (int o = 16; o > 0; o >>= 1) s += __shfl_xor_sync(0xFFFFFFFFu, s, o);
    if (lane == 0) out[b * NC + c] = s + bfc[c];
}

// ---------------- launch ----------------
extern "C" void kernel_launch(void* const* d_in, const int* in_sizes, int n_in,
                              void* d_out, int out_size) {
    (void)in_sizes; (void)n_in; (void)out_size;
    const float* x    = (const float*)d_in[0];
    const float* h1   = (const float*)d_in[1];
    const float* c1   = (const float*)d_in[2];
    const float* h2   = (const float*)d_in[3];
    const float* c2   = (const float*)d_in[4];
    const float* Wih1 = (const float*)d_in[5];
    const float* Whh1 = (const float*)d_in[6];
    const float* bih1 = (const float*)d_in[7];
    const float* bhh1 = (const float*)d_in[8];
    const float* Wih2 = (const float*)d_in[9];
    const float* Whh2 = (const float*)d_in[10];
    const float* bih2 = (const float*)d_in[11];
    const float* bhh2 = (const float*)d_in[12];
    const float* Wfc  = (const float*)d_in[13];
    const float* bfc  = (const float*)d_in[14];
    float* out = (float*)d_out;

    static int smem_set = 0;
    if (!smem_set) {
        cudaFuncSetAttribute(lstm_step_combined, cudaFuncAttributeMaxDynamicSharedMemorySize, SMEM_DYN);
        smem_set = 1;
    }

    // one-time prep (single launch)
    {
        dim3 pgrid((NT * NB * INP + 255) / 256, 6);
        prep_all<<<pgrid, 256>>>(x, h1, c1, h2, c2, bih1, bhh1, bih2, bhh2,
                                 Wih1, Whh1, Wih2, Whh2);
    }

    // recurrence: one combined launch per step boundary
    dim3 grid(G4 / 64, 1, 2);   // 128 CTAs
    for (int tl = 0; tl <= NT; tl++) {
        lstm_step_combined<<<grid, 512, SMEM_DYN>>>(tl);
    }

    fc_kernel<<<dim3(NB, NC), 32>>>(Wfc, bfc, out);
}

// round 14
// speedup vs baseline: 3.6934x; 1.5953x over previous
#include <cuda_runtime.h>
#include <cuda_fp16.h>
#include <cstdint>
#include <cstddef>

// Problem dims
#define NB   128     // batch
#define NT   256     // time steps
#define HD   1024    // hidden
#define IN   150     // input feature (J*D)
#define INP  192     // padded input feature
#define NC   60      // classes
#define G4   4096    // 4*HD

// Packed tile geometry: k-tile = 64 halves (128B rows, SW128 swizzled)
#define KT       64
#define AHALVES  16384          // A tile block: 256 rows (hi 0-127, lo 128-255) x 64 halves
#define WTILEH   (4096 * 64)    // weight tile block: 4096 n-rows x 64 halves
#define XSTEPH   (3 * AHALVES)  // x per step: 3 tiles

// smem stages
#define ATB   32768             // A tile bytes
#define BTB   8192              // B tile bytes
#define STB   (ATB + BTB)       // 40960
#define NST   4
#define SMEM_BODY (NST * STB)   // 163840
#define GS_STRIDE 129
#define SMEM_DYN (SMEM_BODY + 1024 + 512)   // pad for 1KB align + mbar + bias

// ---------------- persistent device state (packed, pre-swizzled) ----------------
__device__ __half g_h1p[2][4 * AHALVES];    // 16 k-tiles... (HD/64=16) -> 16*AHALVES
__device__ __half g_h1p_pad[2][12 * AHALVES]; // (split decl to keep sizes explicit below)
// NOTE: simpler to declare full arrays:
__device__ __half g_h1e[2][16 * AHALVES];
__device__ __half g_h2e[2][16 * AHALVES];
__device__ float g_c1[NB * HD];
__device__ float g_c2[NB * HD];
__device__ float g_bias1e[G4];              // reordered n = u*4+g
__device__ float g_bias2e[G4];
__device__ __half g_whh1p[16 * WTILEH];
__device__ __half g_wih2p[16 * WTILEH];
__device__ __half g_whh2p[16 * WTILEH];
__device__ __half g_wih1p[3 * WTILEH];
__device__ __half g_xp[NT * XSTEPH];

// ---------------- PTX helpers ----------------
__device__ __forceinline__ uint32_t smem_u32(const void* p) {
    uint32_t a;
    asm("{ .reg .u64 t; cvta.to.shared.u64 t, %1; cvt.u32.u64 %0, t; }" : "=r"(a) : "l"(p));
    return a;
}
__device__ __forceinline__ void cpbulk(uint32_t dst, const void* src, uint32_t bytes, uint32_t mbar) {
    asm volatile("cp.async.bulk.shared::cta.global.mbarrier::complete_tx::bytes [%0], [%1], %2, [%3];"
                 :: "r"(dst), "l"(src), "r"(bytes), "r"(mbar) : "memory");
}
#define MBAR_INIT(a, cnt) asm volatile("mbarrier.init.shared.b64 [%0], %1;" :: "r"(a), "r"(cnt) : "memory")
#define MBAR_EXPECT_TX(a, bytes) \
    asm volatile("mbarrier.arrive.expect_tx.shared.b64 _, [%0], %1;" :: "r"(a), "r"((uint32_t)(bytes)) : "memory")
#define MBAR_WAIT(a, par) do {                                                   \
    uint32_t _d = 0;                                                             \
    while (!_d) {                                                                \
        asm volatile("{ .reg .pred p; mbarrier.try_wait.parity.shared.b64 p, [%1], %2; selp.b32 %0,1,0,p; }" \
            : "=r"(_d) : "r"(a), "r"((uint32_t)(par)) : "memory");               \
    }                                                                            \
} while (0)

__device__ __forceinline__ void ldsm4(uint32_t* r, uint32_t addr) {
    asm volatile("ldmatrix.sync.aligned.m8n8.x4.shared.b16 {%0,%1,%2,%3}, [%4];"
                 : "=r"(r[0]), "=r"(r[1]), "=r"(r[2]), "=r"(r[3]) : "r"(addr));
}
__device__ __forceinline__ void mma16816(float* d, const uint32_t* a, const uint32_t* b) {
    asm volatile(
        "mma.sync.aligned.m16n8k16.row.col.f32.f16.f16.f32 "
        "{%0,%1,%2,%3}, {%4,%5,%6,%7}, {%8,%9}, {%0,%1,%2,%3};"
        : "+f"(d[0]), "+f"(d[1]), "+f"(d[2]), "+f"(d[3])
        : "r"(a[0]), "r"(a[1]), "r"(a[2]), "r"(a[3]), "r"(b[0]), "r"(b[1]));
}

__device__ __forceinline__ float sigf(float x) { return 1.0f / (1.0f + __expf(-x)); }
__device__ __forceinline__ float tanh_f(float x) { return 2.0f / (1.0f + __expf(-2.0f * x)) - 1.0f; }

// swizzled half-index within a tile block row: row r, half-col kl (0..63)
__device__ __forceinline__ int swh(int r, int kl) {
    return ((kl * 2) ^ ((r & 7) << 4)) >> 1;
}

// ---------------- single merged prep kernel ----------------
__device__ __forceinline__ void conv_w_packed(const float* W, __half* out, int K, int KP, int idx) {
    if (idx >= G4 * KP) return;
    int n = idx / KP, k = idx % KP;
    int g = n & 3, u = n >> 2;
    float v = (k < K) ? W[(size_t)(g * HD + u) * K + k] : 0.0f;
    int tile = k >> 6, kl = k & 63;
    out[(size_t)tile * WTILEH + (size_t)n * 64 + swh(n, kl)] = __float2half(v);
}

__global__ void prep_all(const float* __restrict__ x,
                         const float* __restrict__ h1, const float* __restrict__ c1,
                         const float* __restrict__ h2, const float* __restrict__ c2,
                         const float* __restrict__ bih1, const float* __restrict__ bhh1,
                         const float* __restrict__ bih2, const float* __restrict__ bhh2,
                         const float* __restrict__ Wih1, const float* __restrict__ Whh1,
                         const float* __restrict__ Wih2, const float* __restrict__ Whh2) {
    int idx = blockIdx.x * blockDim.x + threadIdx.x;
    int task = blockIdx.y;
    if (task == 0) {
        if (idx < NB * HD) {
            int m = idx / HD, u = idx % HD;
            float v1 = h1[idx], v2 = h2[idx];
            __half h1hi = __float2half(v1);
            __half h1lo = __float2half(v1 - __half2float(h1hi));
            __half h2hi = __float2half(v2);
            __half h2lo = __float2half(v2 - __half2float(h2hi));
            int tile = u >> 6, kl = u & 63;
            size_t base = (size_t)tile * AHALVES + (size_t)m * 64 + swh(m, kl);
            g_h1e[0][base] = h1hi; g_h1e[0][base + 8192] = h1lo;
            g_h2e[0][base] = h2hi; g_h2e[0][base + 8192] = h2lo;
            g_c1[idx] = c1[idx];
            g_c2[idx] = c2[idx];
        }
        if (idx < G4) {
            int g = idx & 3, u = idx >> 2;
            int r = g * HD + u;
            g_bias1e[idx] = bih1[r] + bhh1[r];
            g_bias2e[idx] = bih2[r] + bhh2[r];
        }
    } else if (task == 1) {
        conv_w_packed(Whh1, g_whh1p, HD, HD, idx);
    } else if (task == 2) {
        conv_w_packed(Wih2, g_wih2p, HD, HD, idx);
    } else if (task == 3) {
        conv_w_packed(Whh2, g_whh2p, HD, HD, idx);
    } else if (task == 4) {
        conv_w_packed(Wih1, g_wih1p, IN, INP, idx);
    } else {
        if (idx >= NT * NB * INP) return;
        int k = idx % INP;
        int r = idx / INP;
        int b = r % NB, t = r / NB;
        float v = (k < IN) ? x[((size_t)b * NT + t) * IN + k] : 0.0f;
        __half hi = __float2half(v);
        __half lo = __float2half(v - __half2float(hi));
        int tile = k >> 6, kl = k & 63;
        size_t base = (size_t)t * XSTEPH + (size_t)tile * AHALVES + (size_t)b * 64 + swh(b, kl);
        g_xp[base] = hi;
        g_xp[base + 8192] = lo;
    }
}

// ---------------- combined LSTM step kernel ----------------
// tl = 0..NT.  blockIdx.z==1: role1 (phase1 at t=tl-1)  [skip tl==0]
//              blockIdx.z==0: role0 (phase0 at t=tl)    [skip tl==NT]
// grid = (64 n-tiles, 1, 2 roles) = 128 CTAs, 1/SM. block = 512 (16 warps, 16m x 32n).
// Loads: cp.async.bulk (one 32KB A block + one 8KB B block per k-tile) + mbarrier ring.
__global__ void __launch_bounds__(512)
lstm_step_combined(int tl) {
    const int role = blockIdx.z;
    if (role == 0 && tl == NT) return;
    if (role == 1 && tl == 0) return;
    const int t = (role == 0) ? tl : (tl - 1);
    const int cur = t & 1;
    const int n0 = blockIdx.x * 64;

    extern __shared__ __align__(16) char raw[];
    const uint32_t SB = (smem_u32(raw) + 1023u) & ~1023u;
    char* base = raw + (SB - smem_u32(raw));
    float* Gs    = (float*)base;                       // aliases stages (after loop)
    float* biasS = (float*)(base + SMEM_BODY + 64);    // after mbarriers
    const uint32_t MB = SB + SMEM_BODY;                // 4 mbarriers (8B each)

    const int tid  = threadIdx.x;
    const int wid  = tid >> 5;
    const int lane = tid & 31;

    const __half *Ap0, *Ap1, *Bp0, *Bp1;
    const float* biasE;
    float* cst;
    __half* houtP;
    int T1;
    if (role == 0) {
        Ap0 = g_h1e[cur];      Bp0 = g_whh1p;
        Ap1 = g_xp + (size_t)t * XSTEPH;  Bp1 = g_wih1p;
        T1 = 3;
        biasE = g_bias1e; cst = g_c1; houtP = g_h1e[cur ^ 1];
    } else {
        Ap0 = g_h1e[cur ^ 1];  Bp0 = g_wih2p;
        Ap1 = g_h2e[cur];      Bp1 = g_whh2p;
        T1 = 16;
        biasE = g_bias2e; cst = g_c2; houtP = g_h2e[cur ^ 1];
    }
    const int T0 = 16;
    const int TT = T0 + T1;          // 32 or 19

    if (tid == 0) {
#pragma unroll
        for (int s = 0; s < NST; s++) MBAR_INIT(MB + 8 * s, 1);
    }
    __syncthreads();

    auto issue = [&](int c) {
        const int s = c & (NST - 1);
        const __half *sa, *sb;
        if (c < T0) { sa = Ap0 + (size_t)c * AHALVES;        sb = Bp0 + ((size_t)c * 4096 + n0) * 64; }
        else        { sa = Ap1 + (size_t)(c - T0) * AHALVES; sb = Bp1 + ((size_t)(c - T0) * 4096 + n0) * 64; }
        const uint32_t mb = MB + 8u * s;
        MBAR_EXPECT_TX(mb, ATB + BTB);
        cpbulk(SB + s * STB, sa, ATB, mb);
        cpbulk(SB + s * STB + ATB, sb, BTB, mb);
    };
    if (tid == 0) { issue(0); issue(1); issue(2); }

    float biasR = (tid < 64) ? biasE[n0 + tid] : 0.0f;

    // ldmatrix lane maps (SW128 swizzle; rows are 128B)
    const int wr = wid >> 1;      // m sixteenth (0..7), rows wr*16..+15
    const int wc = wid & 1;       // n half
    const int grp = lane >> 3, lr = lane & 7;
    const uint32_t xm = (uint32_t)(lr << 4);
    const uint32_t arowH = (uint32_t)((wr * 16 + lr + (grp & 1) * 8) * 128);
    uint32_t brow[2];
#pragma unroll
    for (int nc = 0; nc < 2; nc++)
        brow[nc] = (uint32_t)((wc * 32 + nc * 16 + lr + (grp >> 1) * 8) * 128) + ATB;
    uint32_t acol[4], bcol[4];
#pragma unroll
    for (int kk = 0; kk < 4; kk++) {
        acol[kk] = (uint32_t)(((grp >> 1) * 16 + kk * 32)) ^ xm;
        bcol[kk] = (uint32_t)(((grp & 1) * 16 + kk * 32)) ^ xm;
    }

    float d[4][4];
#pragma unroll
    for (int nj = 0; nj < 4; nj++)
#pragma unroll
        for (int q = 0; q < 4; q++) d[nj][q] = 0.0f;

    for (int c = 0; c < TT; c++) {
        const int s = c & (NST - 1);
        MBAR_WAIT(MB + 8u * s, (c >> 2) & 1);

        const uint32_t sb = SB + s * STB;
#pragma unroll
        for (int kk = 0; kk < 4; kk++) {
            uint32_t ah[4], al[4], b0r[4], b1r[4];
            ldsm4(b0r, sb + brow[0] + bcol[kk]);
            ldsm4(b1r, sb + brow[1] + bcol[kk]);
            ldsm4(ah,  sb + arowH + acol[kk]);
            ldsm4(al,  sb + arowH + 16384 + acol[kk]);
            mma16816(d[0], ah, b0r + 0);
            mma16816(d[1], ah, b0r + 2);
            mma16816(d[2], ah, b1r + 0);
            mma16816(d[3], ah, b1r + 2);
            mma16816(d[0], al, b0r + 0);
            mma16816(d[1], al, b0r + 2);
            mma16816(d[2], al, b1r + 0);
            mma16816(d[3], al, b1r + 2);
        }
        __syncthreads();   // stage s fully consumed by all warps
        if (tid == 0 && c + 3 < TT) issue(c + 3);
    }

    if (tid < 64) biasS[tid] = biasR;

    // acc -> Gs [n][m]
#pragma unroll
    for (int nj = 0; nj < 4; nj++) {
        int r0 = wr * 16 + (lane >> 2);
        int cb = wc * 32 + nj * 8 + (lane & 3) * 2;
        Gs[cb * GS_STRIDE + r0]           = d[nj][0];
        Gs[(cb + 1) * GS_STRIDE + r0]     = d[nj][1];
        Gs[cb * GS_STRIDE + r0 + 8]       = d[nj][2];
        Gs[(cb + 1) * GS_STRIDE + r0 + 8] = d[nj][3];
    }
    __syncthreads();

    // cell update: 128 m x 16 u = 2048 cells, 4 per thread; h written packed+swizzled
    const int ubase = n0 >> 2;
#pragma unroll
    for (int r = 0; r < 4; r++) {
        int idx = tid + r * 512;
        int ml = idx & 127;     // m
        int u  = idx >> 7;      // 0..15
        int nb = u * 4;
        float gi_ = Gs[(nb + 0) * GS_STRIDE + ml] + biasS[nb + 0];
        float gf_ = Gs[(nb + 1) * GS_STRIDE + ml] + biasS[nb + 1];
        float gg_ = Gs[(nb + 2) * GS_STRIDE + ml] + biasS[nb + 2];
        float go_ = Gs[(nb + 3) * GS_STRIDE + ml] + biasS[nb + 3];
        int ug = ubase + u;
        int off = ml * HD + ug;
        float cv = cst[off];
        float cn = sigf(gf_) * cv + sigf(gi_) * tanh_f(gg_);
        cst[off] = cn;
        float h = sigf(go_) * tanh_f(cn);
        __half hi = __float2half(h);
        __half lo = __float2half(h - __half2float(hi));
        int tile = ug >> 6, kl = ug & 63;
        size_t hb = (size_t)tile * AHALVES + (size_t)ml * 64 + swh(ml, kl);
        houtP[hb] = hi;
        houtP[hb + 8192] = lo;
    }
}

// ---------------- final FC: out = h2 @ Wfc^T + bfc ----------------
__global__ void fc_kernel(const float* __restrict__ Wfc, const float* __restrict__ bfc,
                          float* __restrict__ out) {
    int b = blockIdx.x;
    int c = blockIdx.y;
    int lane = threadIdx.x;
    // last phase1 (t=NT-1, odd) wrote g_h2e[0]
    const __half* he = g_h2e[0];
    const float* w = Wfc + (size_t)c * HD;
    float s = 0.0f;
    for (int k = lane; k < HD; k += 32) {
        int tile = k >> 6, kl = k & 63;
        size_t idx = (size_t)tile * AHALVES + (size_t)b * 64 + swh(b, kl);
        float h = __half2float(he[idx]) + __half2float(he[idx + 8192]);
        s += h * w[k];
    }
#pragma unroll
    for (int o = 16; o > 0; o >>= 1) s += __shfl_xor_sync(0xFFFFFFFFu, s, o);
    if (lane == 0) out[b * NC + c] = s + bfc[c];
}

// ---------------- launch ----------------
extern "C" void kernel_launch(void* const* d_in, const int* in_sizes, int n_in,
                              void* d_out, int out_size) {
    (void)in_sizes; (void)n_in; (void)out_size;
    const float* x    = (const float*)d_in[0];
    const float* h1   = (const float*)d_in[1];
    const float* c1   = (const float*)d_in[2];
    const float* h2   = (const float*)d_in[3];
    const float* c2   = (const float*)d_in[4];
    const float* Wih1 = (const float*)d_in[5];
    const float* Whh1 = (const float*)d_in[6];
    const float* bih1 = (const float*)d_in[7];
    const float* bhh1 = (const float*)d_in[8];
    const float* Wih2 = (const float*)d_in[9];
    const float* Whh2 = (const float*)d_in[10];
    const float* bih2 = (const float*)d_in[11];
    const float* bhh2 = (const float*)d_in[12];
    const float* Wfc  = (const float*)d_in[13];
    const float* bfc  = (const float*)d_in[14];
    float* out = (float*)d_out;

    static int smem_set = 0;
    if (!smem_set) {
        cudaFuncSetAttribute(lstm_step_combined, cudaFuncAttributeMaxDynamicSharedMemorySize, SMEM_DYN);
        smem_set = 1;
    }

    // one-time prep (single launch)
    {
        dim3 pgrid((NT * NB * INP + 255) / 256, 6);
        prep_all<<<pgrid, 256>>>(x, h1, c1, h2, c2, bih1, bhh1, bih2, bhh2,
                                 Wih1, Whh1, Wih2, Whh2);
    }

    // recurrence: one combined launch per step boundary
    dim3 grid(G4 / 64, 1, 2);   // 128 CTAs
    for (int tl = 0; tl <= NT; tl++) {
        lstm_step_combined<<<grid, 512, SMEM_DYN>>>(tl);
    }

    fc_kernel<<<dim3(NB, NC), 32>>>(Wfc, bfc, out);
}

// round 15
// speedup vs baseline: 4.0072x; 1.0849x over previous
#include <cuda_runtime.h>
#include <cuda_fp16.h>
#include <cstdint>
#include <cstddef>

// Problem dims
#define NB   128     // batch
#define NT   256     // time steps
#define HD   1024    // hidden
#define IN   150     // input feature (J*D)
#define INP  192     // padded input feature
#define NC   60      // classes
#define G4   4096    // 4*HD

// Packed tile geometry: k-tile = 64 halves (128B rows, SW128 swizzled)
#define KT       64
#define AHALVES  16384          // A tile block: 256 rows (hi 0-127, lo 128-255) x 64 halves
#define WTILEH   (4096 * 64)    // weight tile block: 4096 n-rows x 64 halves
#define XSTEPH   (3 * AHALVES)  // x per step: 3 tiles

// smem stages
#define ATB   32768             // A tile bytes
#define BTB   8192              // B tile bytes
#define STB   (ATB + BTB)       // 40960
#define NST   4
#define SMEM_BODY (NST * STB)   // 163840
#define GS_STRIDE 129
#define SMEM_DYN (SMEM_BODY + 1024 + 512)   // pad for 1KB align + mbars + bias

// ---------------- persistent device state (packed, pre-swizzled) ----------------
__device__ __half g_h1e[2][16 * AHALVES];
__device__ __half g_h2e[2][16 * AHALVES];
__device__ float g_c1[NB * HD];
__device__ float g_c2[NB * HD];
__device__ float g_bias1e[G4];              // reordered n = u*4+g
__device__ float g_bias2e[G4];
__device__ __half g_whh1p[16 * WTILEH];
__device__ __half g_wih2p[16 * WTILEH];
__device__ __half g_whh2p[16 * WTILEH];
__device__ __half g_wih1p[3 * WTILEH];
__device__ __half g_xp[NT * XSTEPH];

// ---------------- PTX helpers ----------------
__device__ __forceinline__ uint32_t smem_u32(const void* p) {
    uint32_t a;
    asm("{ .reg .u64 t; cvta.to.shared.u64 t, %1; cvt.u32.u64 %0, t; }" : "=r"(a) : "l"(p));
    return a;
}
__device__ __forceinline__ void cpbulk(uint32_t dst, const void* src, uint32_t bytes, uint32_t mbar) {
    asm volatile("cp.async.bulk.shared::cta.global.mbarrier::complete_tx::bytes [%0], [%1], %2, [%3];"
                 :: "r"(dst), "l"(src), "r"(bytes), "r"(mbar) : "memory");
}
#define MBAR_INIT(a, cnt) asm volatile("mbarrier.init.shared.b64 [%0], %1;" :: "r"(a), "r"(cnt) : "memory")
#define MBAR_EXPECT_TX(a, bytes) \
    asm volatile("mbarrier.arrive.expect_tx.shared.b64 _, [%0], %1;" :: "r"(a), "r"((uint32_t)(bytes)) : "memory")
#define MBAR_ARRIVE(a) \
    asm volatile("mbarrier.arrive.shared.b64 _, [%0];" :: "r"(a) : "memory")
#define MBAR_WAIT(a, par) do {                                                   \
    uint32_t _d = 0;                                                             \
    while (!_d) {                                                                \
        asm volatile("{ .reg .pred p; mbarrier.try_wait.parity.shared.b64 p, [%1], %2; selp.b32 %0,1,0,p; }" \
            : "=r"(_d) : "r"(a), "r"((uint32_t)(par)) : "memory");               \
    }                                                                            \
} while (0)

__device__ __forceinline__ void ldsm4(uint32_t* r, uint32_t addr) {
    asm volatile("ldmatrix.sync.aligned.m8n8.x4.shared.b16 {%0,%1,%2,%3}, [%4];"
                 : "=r"(r[0]), "=r"(r[1]), "=r"(r[2]), "=r"(r[3]) : "r"(addr));
}
__device__ __forceinline__ void mma16816(float* d, const uint32_t* a, const uint32_t* b) {
    asm volatile(
        "mma.sync.aligned.m16n8k16.row.col.f32.f16.f16.f32 "
        "{%0,%1,%2,%3}, {%4,%5,%6,%7}, {%8,%9}, {%0,%1,%2,%3};"
        : "+f"(d[0]), "+f"(d[1]), "+f"(d[2]), "+f"(d[3])
        : "r"(a[0]), "r"(a[1]), "r"(a[2]), "r"(a[3]), "r"(b[0]), "r"(b[1]));
}

__device__ __forceinline__ float sigf(float x) { return 1.0f / (1.0f + __expf(-x)); }
__device__ __forceinline__ float tanh_f(float x) { return 2.0f / (1.0f + __expf(-2.0f * x)) - 1.0f; }

// swizzled half-index within a tile block row: row r, half-col kl (0..63)
__device__ __forceinline__ int swh(int r, int kl) {
    return ((kl * 2) ^ ((r & 7) << 4)) >> 1;
}

// ---------------- single merged prep kernel ----------------
__device__ __forceinline__ void conv_w_packed(const float* W, __half* out, int K, int KP, int idx) {
    if (idx >= G4 * KP) return;
    int n = idx / KP, k = idx % KP;
    int g = n & 3, u = n >> 2;
    float v = (k < K) ? W[(size_t)(g * HD + u) * K + k] : 0.0f;
    int tile = k >> 6, kl = k & 63;
    out[(size_t)tile * WTILEH + (size_t)n * 64 + swh(n, kl)] = __float2half(v);
}

__global__ void prep_all(const float* __restrict__ x,
                         const float* __restrict__ h1, const float* __restrict__ c1,
                         const float* __restrict__ h2, const float* __restrict__ c2,
                         const float* __restrict__ bih1, const float* __restrict__ bhh1,
                         const float* __restrict__ bih2, const float* __restrict__ bhh2,
                         const float* __restrict__ Wih1, const float* __restrict__ Whh1,
                         const float* __restrict__ Wih2, const float* __restrict__ Whh2) {
    int idx = blockIdx.x * blockDim.x + threadIdx.x;
    int task = blockIdx.y;
    if (task == 0) {
        if (idx < NB * HD) {
            int m = idx / HD, u = idx % HD;
            float v1 = h1[idx], v2 = h2[idx];
            __half h1hi = __float2half(v1);
            __half h1lo = __float2half(v1 - __half2float(h1hi));
            __half h2hi = __float2half(v2);
            __half h2lo = __float2half(v2 - __half2float(h2hi));
            int tile = u >> 6, kl = u & 63;
            size_t base = (size_t)tile * AHALVES + (size_t)m * 64 + swh(m, kl);
            g_h1e[0][base] = h1hi; g_h1e[0][base + 8192] = h1lo;
            g_h2e[0][base] = h2hi; g_h2e[0][base + 8192] = h2lo;
            g_c1[idx] = c1[idx];
            g_c2[idx] = c2[idx];
        }
        if (idx < G4) {
            int g = idx & 3, u = idx >> 2;
            int r = g * HD + u;
            g_bias1e[idx] = bih1[r] + bhh1[r];
            g_bias2e[idx] = bih2[r] + bhh2[r];
        }
    } else if (task == 1) {
        conv_w_packed(Whh1, g_whh1p, HD, HD, idx);
    } else if (task == 2) {
        conv_w_packed(Wih2, g_wih2p, HD, HD, idx);
    } else if (task == 3) {
        conv_w_packed(Whh2, g_whh2p, HD, HD, idx);
    } else if (task == 4) {
        conv_w_packed(Wih1, g_wih1p, IN, INP, idx);
    } else {
        if (idx >= NT * NB * INP) return;
        int k = idx % INP;
        int r = idx / INP;
        int b = r % NB, t = r / NB;
        float v = (k < IN) ? x[((size_t)b * NT + t) * IN + k] : 0.0f;
        __half hi = __float2half(v);
        __half lo = __float2half(v - __half2float(hi));
        int tile = k >> 6, kl = k & 63;
        size_t base = (size_t)t * XSTEPH + (size_t)tile * AHALVES + (size_t)b * 64 + swh(b, kl);
        g_xp[base] = hi;
        g_xp[base + 8192] = lo;
    }
}

// ---------------- combined LSTM step kernel ----------------
// tl = 0..NT.  blockIdx.z==1: role1 (phase1 at t=tl-1)  [skip tl==0]
//              blockIdx.z==0: role0 (phase0 at t=tl)    [skip tl==NT]
// grid = (64 n-tiles, 1, 2 roles) = 128 CTAs, 1/SM. block = 512 (16 warps, 16m x 32n).
// Producer/consumer mbarrier pipeline: full[s] (tx, count 1) + empty[s] (count 16).
// NO __syncthreads in the mainloop — warps may skew up to 3 tiles.
__global__ void __launch_bounds__(512)
lstm_step_combined(int tl) {
    const int role = blockIdx.z;
    if (role == 0 && tl == NT) return;
    if (role == 1 && tl == 0) return;
    const int t = (role == 0) ? tl : (tl - 1);
    const int cur = t & 1;
    const int n0 = blockIdx.x * 64;

    extern __shared__ __align__(16) char raw[];
    const uint32_t SB = (smem_u32(raw) + 1023u) & ~1023u;
    char* base = raw + (SB - smem_u32(raw));
    float* Gs    = (float*)base;                       // aliases stages (after loop)
    float* biasS = (float*)(base + SMEM_BODY + 128);   // after mbarriers
    const uint32_t MBF = SB + SMEM_BODY;               // 4 full barriers
    const uint32_t MBE = MBF + 32;                     // 4 empty barriers

    const int tid  = threadIdx.x;
    const int wid  = tid >> 5;
    const int lane = tid & 31;

    const __half *Ap0, *Ap1, *Bp0, *Bp1;
    const float* biasE;
    float* cst;
    __half* houtP;
    int T1;
    if (role == 0) {
        Ap0 = g_h1e[cur];      Bp0 = g_whh1p;
        Ap1 = g_xp + (size_t)t * XSTEPH;  Bp1 = g_wih1p;
        T1 = 3;
        biasE = g_bias1e; cst = g_c1; houtP = g_h1e[cur ^ 1];
    } else {
        Ap0 = g_h1e[cur ^ 1];  Bp0 = g_wih2p;
        Ap1 = g_h2e[cur];      Bp1 = g_whh2p;
        T1 = 16;
        biasE = g_bias2e; cst = g_c2; houtP = g_h2e[cur ^ 1];
    }
    const int T0 = 16;
    const int TT = T0 + T1;          // 32 or 19

    if (tid == 0) {
#pragma unroll
        for (int s = 0; s < NST; s++) {
            MBAR_INIT(MBF + 8 * s, 1);
            MBAR_INIT(MBE + 8 * s, 16);
        }
    }
    __syncthreads();

    auto issue = [&](int c) {
        const int s = c & (NST - 1);
        const __half *sa, *sb;
        if (c < T0) { sa = Ap0 + (size_t)c * AHALVES;        sb = Bp0 + ((size_t)c * 4096 + n0) * 64; }
        else        { sa = Ap1 + (size_t)(c - T0) * AHALVES; sb = Bp1 + ((size_t)(c - T0) * 4096 + n0) * 64; }
        const uint32_t mb = MBF + 8u * s;
        MBAR_EXPECT_TX(mb, ATB + BTB);
        cpbulk(SB + s * STB, sa, ATB, mb);
        cpbulk(SB + s * STB + ATB, sb, BTB, mb);
    };
    if (tid == 0) { issue(0); issue(1); issue(2); }

    float biasR = (tid < 64) ? biasE[n0 + tid] : 0.0f;

    // ldmatrix lane maps (SW128 swizzle; rows are 128B)
    const int wr = wid >> 1;      // m sixteenth (0..7), rows wr*16..+15
    const int wc = wid & 1;       // n half
    const int grp = lane >> 3, lr = lane & 7;
    const uint32_t xm = (uint32_t)(lr << 4);
    const uint32_t arowH = (uint32_t)((wr * 16 + lr + (grp & 1) * 8) * 128);
    uint32_t brow[2];
#pragma unroll
    for (int nc = 0; nc < 2; nc++)
        brow[nc] = (uint32_t)((wc * 32 + nc * 16 + lr + (grp >> 1) * 8) * 128) + ATB;
    uint32_t acol[4], bcol[4];
#pragma unroll
    for (int kk = 0; kk < 4; kk++) {
        acol[kk] = (uint32_t)(((grp >> 1) * 16 + kk * 32)) ^ xm;
        bcol[kk] = (uint32_t)(((grp & 1) * 16 + kk * 32)) ^ xm;
    }

    float d[4][4];
#pragma unroll
    for (int nj = 0; nj < 4; nj++)
#pragma unroll
        for (int q = 0; q < 4; q++) d[nj][q] = 0.0f;

    for (int c = 0; c < TT; c++) {
        const int s = c & (NST - 1);

        // producer: refill stage (c+3)&3 once its previous consumer (tile c-1)
        // has been drained by all 16 warps.
        if (tid == 0 && c + 3 < TT) {
            if (c >= 1) {
                const int cn = c + 3;                       // tile being issued
                MBAR_WAIT(MBE + 8u * (cn & (NST - 1)), (uint32_t)(((cn >> 2) - 1) & 1));
            }
            issue(c + 3);
        }

        // consumer: wait for this tile's data
        MBAR_WAIT(MBF + 8u * s, (uint32_t)((c >> 2) & 1));

        const uint32_t sb = SB + s * STB;
#pragma unroll
        for (int kk = 0; kk < 4; kk++) {
            uint32_t ah[4], al[4], b0r[4], b1r[4];
            ldsm4(b0r, sb + brow[0] + bcol[kk]);
            ldsm4(b1r, sb + brow[1] + bcol[kk]);
            ldsm4(ah,  sb + arowH + acol[kk]);
            ldsm4(al,  sb + arowH + 16384 + acol[kk]);
            mma16816(d[0], ah, b0r + 0);
            mma16816(d[1], ah, b0r + 2);
            mma16816(d[2], ah, b1r + 0);
            mma16816(d[3], ah, b1r + 2);
            mma16816(d[0], al, b0r + 0);
            mma16816(d[1], al, b0r + 2);
            mma16816(d[2], al, b1r + 0);
            mma16816(d[3], al, b1r + 2);
        }
        if (lane == 0) MBAR_ARRIVE(MBE + 8u * s);   // this warp done with stage s
    }
    __syncthreads();   // re-converge warps; stage smem now reusable as Gs

    if (tid < 64) biasS[tid] = biasR;

    // acc -> Gs [n][m]
#pragma unroll
    for (int nj = 0; nj < 4; nj++) {
        int r0 = wr * 16 + (lane >> 2);
        int cb = wc * 32 + nj * 8 + (lane & 3) * 2;
        Gs[cb * GS_STRIDE + r0]           = d[nj][0];
        Gs[(cb + 1) * GS_STRIDE + r0]     = d[nj][1];
        Gs[cb * GS_STRIDE + r0 + 8]       = d[nj][2];
        Gs[(cb + 1) * GS_STRIDE + r0 + 8] = d[nj][3];
    }
    __syncthreads();

    // cell update: 128 m x 16 u = 2048 cells, 4 per thread; h written packed+swizzled
    const int ubase = n0 >> 2;
#pragma unroll
    for (int r = 0; r < 4; r++) {
        int idx = tid + r * 512;
        int ml = idx & 127;     // m
        int u  = idx >> 7;      // 0..15
        int nb = u * 4;
        float gi_ = Gs[(nb + 0) * GS_STRIDE + ml] + biasS[nb + 0];
        float gf_ = Gs[(nb + 1) * GS_STRIDE + ml] + biasS[nb + 1];
        float gg_ = Gs[(nb + 2) * GS_STRIDE + ml] + biasS[nb + 2];
        float go_ = Gs[(nb + 3) * GS_STRIDE + ml] + biasS[nb + 3];
        int ug = ubase + u;
        int off = ml * HD + ug;
        float cv = cst[off];
        float cn = sigf(gf_) * cv + sigf(gi_) * tanh_f(gg_);
        cst[off] = cn;
        float h = sigf(go_) * tanh_f(cn);
        __half hi = __float2half(h);
        __half lo = __float2half(h - __half2float(hi));
        int tile = ug >> 6, kl = ug & 63;
        size_t hb = (size_t)tile * AHALVES + (size_t)ml * 64 + swh(ml, kl);
        houtP[hb] = hi;
        houtP[hb + 8192] = lo;
    }
}

// ---------------- final FC: out = h2 @ Wfc^T + bfc ----------------
__global__ void fc_kernel(const float* __restrict__ Wfc, const float* __restrict__ bfc,
                          float* __restrict__ out) {
    int b = blockIdx.x;
    int c = blockIdx.y;
    int lane = threadIdx.x;
    // last phase1 (t=NT-1, odd) wrote g_h2e[0]
    const __half* he = g_h2e[0];
    const float* w = Wfc + (size_t)c * HD;
    float s = 0.0f;
    for (int k = lane; k < HD; k += 32) {
        int tile = k >> 6, kl = k & 63;
        size_t idx = (size_t)tile * AHALVES + (size_t)b * 64 + swh(b, kl);
        float h = __half2float(he[idx]) + __half2float(he[idx + 8192]);
        s += h * w[k];
    }
#pragma unroll
    for (int o = 16; o > 0; o >>= 1) s += __shfl_xor_sync(0xFFFFFFFFu, s, o);
    if (lane == 0) out[b * NC + c] = s + bfc[c];
}

// ---------------- launch ----------------
extern "C" void kernel_launch(void* const* d_in, const int* in_sizes, int n_in,
                              void* d_out, int out_size) {
    (void)in_sizes; (void)n_in; (void)out_size;
    const float* x    = (const float*)d_in[0];
    const float* h1   = (const float*)d_in[1];
    const float* c1   = (const float*)d_in[2];
    const float* h2   = (const float*)d_in[3];
    const float* c2   = (const float*)d_in[4];
    const float* Wih1 = (const float*)d_in[5];
    const float* Whh1 = (const float*)d_in[6];
    const float* bih1 = (const float*)d_in[7];
    const float* bhh1 = (const float*)d_in[8];
    const float* Wih2 = (const float*)d_in[9];
    const float* Whh2 = (const float*)d_in[10];
    const float* bih2 = (const float*)d_in[11];
    const float* bhh2 = (const float*)d_in[12];
    const float* Wfc  = (const float*)d_in[13];
    const float* bfc  = (const float*)d_in[14];
    float* out = (float*)d_out;

    static int smem_set = 0;
    if (!smem_set) {
        cudaFuncSetAttribute(lstm_step_combined, cudaFuncAttributeMaxDynamicSharedMemorySize, SMEM_DYN);
        smem_set = 1;
    }

    // one-time prep (single launch)
    {
        dim3 pgrid((NT * NB * INP + 255) / 256, 6);
        prep_all<<<pgrid, 256>>>(x, h1, c1, h2, c2, bih1, bhh1, bih2, bhh2,
                                 Wih1, Whh1, Wih2, Whh2);
    }

    // recurrence: one combined launch per step boundary
    dim3 grid(G4 / 64, 1, 2);   // 128 CTAs
    for (int tl = 0; tl <= NT; tl++) {
        lstm_step_combined<<<grid, 512, SMEM_DYN>>>(tl);
    }

    fc_kernel<<<dim3(NB, NC), 32>>>(Wfc, bfc, out);
}